// round 6
// baseline (speedup 1.0000x reference)
#include <cuda_runtime.h>
#include <cuda_fp16.h>
#include <cstdint>

#define BATCH 8
#define NNODE 2048
#define FEAT  128
#define LOG2E 1.4426950408889634f

// ---------------- device scratch (no allocations allowed) -------------------
__device__ __half g_wht[BATCH * FEAT * NNODE];  // WhT fp16, [b][f][n]
__device__ float g_wh1[BATCH * NNODE];          // Wh1 * LOG2E
__device__ float g_wh2[BATCH * NNODE];          // Wh2 * LOG2E
__device__ float g_w2bmax[BATCH * 16];          // per 128-block max of g_wh2
__device__ float g_u1[FEAT], g_u2[FEAT], g_c[2];

// ---------------- helpers ---------------------------------------------------
__device__ __forceinline__ float leakyf(float x) { return fmaxf(x, 0.2f * x); }

__device__ __forceinline__ float ex2f(float x) {
    float r;
    asm("ex2.approx.ftz.f32 %0, %1;" : "=f"(r) : "f"(x));
    return r;
}

__device__ __forceinline__ uint32_t smem_u32(const void* p) {
    uint32_t a;
    asm("{ .reg .u64 t; cvta.to.shared.u64 t, %1; cvt.u32.u64 %0, t; }"
        : "=r"(a) : "l"(p));
    return a;
}

__device__ __forceinline__ uint32_t pack_h2(float x, float y) {
    __half2 v = __floats2half2_rn(x, y);
    return *reinterpret_cast<uint32_t*>(&v);
}

#define LDSM4(r, a)                                                            \
    asm volatile(                                                              \
        "ldmatrix.sync.aligned.m8n8.x4.shared.b16 {%0,%1,%2,%3}, [%4];"        \
        : "=r"((r)[0]), "=r"((r)[1]), "=r"((r)[2]), "=r"((r)[3])               \
        : "r"(a))

#define MMA16816(c, A, B0, B1)                                                 \
    asm volatile(                                                              \
        "mma.sync.aligned.m16n8k16.row.col.f32.f16.f16.f32 "                   \
        "{%0,%1,%2,%3}, {%4,%5,%6,%7}, {%8,%9}, {%0,%1,%2,%3};"                \
        : "+f"((c)[0]), "+f"((c)[1]), "+f"((c)[2]), "+f"((c)[3])               \
        : "r"((A)[0]), "r"((A)[1]), "r"((A)[2]), "r"((A)[3]),                  \
          "r"(B0), "r"(B1))

// ============================================================================
// k_prep: u1 = W^T a1, u2 = W^T a2, c1 = b.a1, c2 = b.a2
// ============================================================================
__global__ void k_prep(const float* __restrict__ W, const float* __restrict__ Wb,
                       const float* __restrict__ aw) {
    const int k = threadIdx.x;  // 0..127
    float s1 = 0.f, s2 = 0.f;
#pragma unroll 4
    for (int f = 0; f < FEAT; f++) {
        float w = W[f * FEAT + k];
        s1 = fmaf(aw[f], w, s1);
        s2 = fmaf(aw[FEAT + f], w, s2);
    }
    g_u1[k] = s1;
    g_u2[k] = s2;

    __shared__ float r1[128], r2[128];
    r1[k] = Wb[k] * aw[k];
    r2[k] = Wb[k] * aw[FEAT + k];
    __syncthreads();
    if (k < 64) { r1[k] += r1[k + 64]; r2[k] += r2[k + 64]; }
    __syncthreads();
    if (k == 0) {
        float c1 = 0.f, c2 = 0.f;
#pragma unroll
        for (int i = 0; i < 64; i++) { c1 += r1[i]; c2 += r2[i]; }
        g_c[0] = c1;
        g_c[1] = c2;
    }
}

// ============================================================================
// k_linear: WhT[f][n] = sum_k W[f][k] h[n][k] + b[f]  via fp16 mma.sync.
// Scores via fp32 GEMV against u1/u2 (exact path). grid (16,8), 256 thr.
// ============================================================================
static constexpr int LIN_SMEM = 1024 + 128 * 132 * 4 + 2 * 32768;  // 134144

__global__ __launch_bounds__(256, 1) void k_linear(
    const float* __restrict__ h, const float* __restrict__ W,
    const float* __restrict__ Wb) {
    extern __shared__ __align__(16) char dynL[];
    float* u1s = (float*)dynL;            // 128
    float* u2s = u1s + 128;               // 128
    float* wm = u2s + 128;                // 8 warp maxes
    float* h32 = (float*)(dynL + 1024);   // [128][132]
    char* At = dynL + 1024 + 128 * 132 * 4;
    char* Bt = At + 32768;

    const int b = blockIdx.y, n0 = blockIdx.x * 128;
    const int t = threadIdx.x, lane = t & 31, wid = t >> 5;

    if (t < 128) { u1s[t] = g_u1[t]; u2s[t] = g_u2[t]; }

    // stage: h fp32 -> h32 ; W fp32 -> fp16 swizzled A tile
#pragma unroll
    for (int i = 0; i < 8; i++) {
        int idx = t + i * 256;  // chunk id 0..2047
        int row = idx >> 4;
        int x = idx & 15;
        const float* hp = &h[((size_t)(b * NNODE + n0 + row)) * FEAT + x * 8];
        float4 h0 = *(const float4*)hp;
        float4 h1 = *(const float4*)(hp + 4);
        *(float4*)&h32[row * 132 + x * 8] = h0;
        *(float4*)&h32[row * 132 + x * 8 + 4] = h1;
        const float* wp = &W[(size_t)row * FEAT + x * 8];
        float4 w0 = *(const float4*)wp;
        float4 w1 = *(const float4*)(wp + 4);
        uint4 pw;
        pw.x = pack_h2(w0.x, w0.y); pw.y = pack_h2(w0.z, w0.w);
        pw.z = pack_h2(w1.x, w1.y); pw.w = pack_h2(w1.z, w1.w);
        *(uint4*)(At + row * 256 + (((uint32_t)(x ^ (row & 7))) << 4)) = pw;
    }
    __syncthreads();

    // B tile (h fp16) from h32
#pragma unroll
    for (int i = 0; i < 8; i++) {
        int idx = t + i * 256;
        int row = idx >> 4;
        int x = idx & 15;
        float4 a0 = *(float4*)&h32[row * 132 + x * 8];
        float4 a1 = *(float4*)&h32[row * 132 + x * 8 + 4];
        uint4 p;
        p.x = pack_h2(a0.x, a0.y); p.y = pack_h2(a0.z, a0.w);
        p.z = pack_h2(a1.x, a1.y); p.w = pack_h2(a1.z, a1.w);
        *(uint4*)(Bt + row * 256 + (((uint32_t)(x ^ (row & 7))) << 4)) = p;
    }

    // GEMV: scores (fp32 exact)
    {
        const int row = t >> 1, k0 = (t & 1) * 64;
        float p1 = 0.f, p2 = 0.f;
#pragma unroll 8
        for (int k = 0; k < 64; k++) {
            float hv = h32[row * 132 + k0 + k];
            p1 = fmaf(hv, u1s[k0 + k], p1);
            p2 = fmaf(hv, u2s[k0 + k], p2);
        }
        p1 += __shfl_xor_sync(~0u, p1, 1);
        p2 += __shfl_xor_sync(~0u, p2, 1);
        float w2L = (p2 + g_c[1]) * LOG2E;
        if ((t & 1) == 0) {
            g_wh1[b * NNODE + n0 + row] = (p1 + g_c[0]) * LOG2E;
            g_wh2[b * NNODE + n0 + row] = w2L;
        }
        float m = w2L;
#pragma unroll
        for (int o = 16; o >= 1; o >>= 1)
            m = fmaxf(m, __shfl_xor_sync(~0u, m, o));
        if (lane == 0) wm[wid] = m;
    }
    __syncthreads();  // covers Bt staging + wm
    if (t == 0) {
        float mm = wm[0];
#pragma unroll
        for (int i = 1; i < 8; i++) mm = fmaxf(mm, wm[i]);
        g_w2bmax[b * 16 + blockIdx.x] = mm;
    }

    // ---- MMA: warp owns 16 f-rows, N=128 ----
    float acc[16][4];
#pragma unroll
    for (int nt = 0; nt < 16; nt++)
#pragma unroll
        for (int q = 0; q < 4; q++) acc[nt][q] = 0.f;

    const uint32_t At_a = smem_u32(At), Bt_a = smem_u32(Bt);
    const uint32_t aoff = (uint32_t)(wid * 16 + (lane & 7) + ((lane >> 3) & 1) * 8) * 256u;
    const uint32_t a_hk = lane >> 4, a_sw = lane & 7;
    const uint32_t boff = (uint32_t)(((lane >> 4) & 1) * 8 + (lane & 7)) * 256u;
    const uint32_t b_hk = (lane >> 3) & 1, b_sw = lane & 7;

#pragma unroll
    for (int kk = 0; kk < 8; kk++) {
        uint32_t ah[4];
        LDSM4(ah, At_a + aoff + ((((uint32_t)(kk * 2) + a_hk) ^ a_sw) << 4));
        uint32_t cb = (((uint32_t)(kk * 2) + b_hk) ^ b_sw) << 4;
#pragma unroll
        for (int ntp = 0; ntp < 8; ntp++) {
            uint32_t bh[4];
            LDSM4(bh, Bt_a + boff + (uint32_t)ntp * 4096u + cb);
            MMA16816(acc[ntp * 2], ah, bh[0], bh[1]);
            MMA16816(acc[ntp * 2 + 1], ah, bh[2], bh[3]);
        }
    }

    // epilogue: +bias, pack fp16, store WhT
    const int rA = wid * 16 + (lane >> 2), rB = rA + 8, q = lane & 3;
    const float biasA = Wb[rA], biasB = Wb[rB];
#pragma unroll
    for (int nt = 0; nt < 16; nt++) {
        uint32_t pa = pack_h2(acc[nt][0] + biasA, acc[nt][1] + biasA);
        uint32_t pb = pack_h2(acc[nt][2] + biasB, acc[nt][3] + biasB);
        *(uint32_t*)&g_wht[((size_t)(b * FEAT + rA)) * NNODE + n0 + nt * 8 + q * 2] = pa;
        *(uint32_t*)&g_wht[((size_t)(b * FEAT + rB)) * NNODE + n0 + nt * 8 + q * 2] = pb;
    }
}

// ============================================================================
// k_attn: per CTA = 128 query rows, 8 warps x 16 rows, full-width fp32 accum.
// One barrier per chunk; B tile double-buffered; A (P) tile warp-private.
// ============================================================================
static constexpr int ATTN_SMEM = 1024 + 3 * 32768;  // 99328

__global__ __launch_bounds__(256, 1) void k_attn(const int* __restrict__ adj,
                                                 float* __restrict__ out) {
    extern __shared__ __align__(16) char dyn[];
    float* rowsum = (float*)dyn;            // 128 floats
    float* mxs = (float*)(dyn + 512);       // 16 floats
    char* atile = dyn + 1024;
    char* btile0 = atile + 32768;
    char* btile1 = btile0 + 32768;

    const int t = threadIdx.x;
    const int wid = t >> 5, lane = t & 31;
    const int b = blockIdx.x >> 4;
    const int n0 = (blockIdx.x & 15) << 7;

    if (t < 16) mxs[t] = g_w2bmax[b * 16 + t];
    __syncthreads();
    float mxL = mxs[0];
#pragma unroll
    for (int i = 1; i < 16; i++) mxL = fmaxf(mxL, mxs[i]);

    // per-row constants (log2 domain): y = max(c1+w2L, c2+0.2*w2L)
    float c1r[16], c2r[16];
#pragma unroll
    for (int rr = 0; rr < 16; rr++) {
        float w1L = g_wh1[b * NNODE + n0 + wid * 16 + rr];
        float xL = w1L + mxL;
        float MrL = fmaxf(xL, 0.2f * xL);
        c1r[rr] = w1L - MrL;
        c2r[rr] = 0.2f * w1L - MrL;
    }

    float acc[16][4];
#pragma unroll
    for (int nt = 0; nt < 16; nt++)
#pragma unroll
        for (int q = 0; q < 4; q++) acc[nt][q] = 0.f;
    float s_acc[16];
#pragma unroll
    for (int rr = 0; rr < 16; rr++) s_acc[rr] = 0.f;

    const uint32_t atile_a = smem_u32(atile);
    const uint32_t aoff = (uint32_t)(wid * 16 + (lane & 7) + ((lane >> 3) & 1) * 8) * 256u;
    const uint32_t a_hk = lane >> 4, a_sw = lane & 7;
    const uint32_t boff = (uint32_t)(((lane >> 4) & 1) * 8 + (lane & 7)) * 256u;
    const uint32_t b_hk = (lane >> 3) & 1, b_sw = lane & 7;
    const uint32_t p_chunk = (uint32_t)(lane >> 1);
    const uint32_t p_half = (uint32_t)(lane & 1) * 8;
    const int jj = (lane & 15) * 8;
    const int bhalf = lane >> 4;

    auto stage_b = [&](int cc, char* buf) {
#pragma unroll
        for (int it = 0; it < 8; it++) {
            int f = wid * 16 + it * 2 + bhalf;
            uint4 vh = *(const uint4*)&g_wht[((size_t)(b * FEAT + f)) * NNODE + cc * 128 + jj];
            *(uint4*)(buf + (uint32_t)f * 256u +
                      ((((uint32_t)(lane & 15)) ^ (uint32_t)(f & 7)) << 4)) = vh;
        }
    };

    auto compute_p = [&](int cc) {
        const int j0 = cc * 128;
        const float4 w2v = *(const float4*)&g_wh2[b * NNODE + j0 + lane * 4];
        const float w2sx = 0.2f * w2v.x, w2sy = 0.2f * w2v.y;
        const float w2sz = 0.2f * w2v.z, w2sw = 0.2f * w2v.w;
#pragma unroll
        for (int rr = 0; rr < 16; rr++) {
            const int r = wid * 16 + rr;
            const float c1 = c1r[rr], c2 = c2r[rr];
            const int4 av = *(const int4*)&adj[((size_t)(b * NNODE + n0 + r)) * NNODE + j0 + lane * 4];
            float e0 = ex2f(fmaxf(c1 + w2v.x, c2 + w2sx));
            float e1 = ex2f(fmaxf(c1 + w2v.y, c2 + w2sy));
            float e2 = ex2f(fmaxf(c1 + w2v.z, c2 + w2sz));
            float e3 = ex2f(fmaxf(c1 + w2v.w, c2 + w2sw));
            float p0 = av.x ? e0 : 0.f;
            float p1 = av.y ? e1 : 0.f;
            float p2 = av.z ? e2 : 0.f;
            float p3 = av.w ? e3 : 0.f;
            uint2 uh = make_uint2(pack_h2(p0, p1), pack_h2(p2, p3));
            *(uint2*)(atile + (uint32_t)r * 256u +
                      ((p_chunk ^ (uint32_t)(r & 7)) << 4) + p_half) = uh;
            s_acc[rr] += (p0 + p1) + (p2 + p3);
        }
    };

    // prologue: B0 + P0
    stage_b(0, btile0);
    compute_p(0);
    __syncthreads();

#pragma unroll 1
    for (int c = 0; c < 16; c++) {
        const uint32_t bt_a = smem_u32((c & 1) ? btile1 : btile0);
        // ---- MMA on chunk c ----
#pragma unroll 1
        for (int kk = 0; kk < 8; kk++) {
            uint32_t ah[4];
            LDSM4(ah, atile_a + aoff + ((((uint32_t)(kk * 2) + a_hk) ^ a_sw) << 4));
            uint32_t cb = (((uint32_t)(kk * 2) + b_hk) ^ b_sw) << 4;
#pragma unroll
            for (int ntp = 0; ntp < 8; ntp++) {
                uint32_t bh[4];
                LDSM4(bh, bt_a + boff + (uint32_t)ntp * 4096u + cb);
                MMA16816(acc[ntp * 2], ah, bh[0], bh[1]);
                MMA16816(acc[ntp * 2 + 1], ah, bh[2], bh[3]);
            }
        }
        if (c < 15) {
            stage_b(c + 1, (c & 1) ? btile0 : btile1);
            compute_p(c + 1);
            __syncthreads();
        }
    }

    // rowsum reduction
#pragma unroll
    for (int rr = 0; rr < 16; rr++) {
        float s = s_acc[rr];
#pragma unroll
        for (int o = 16; o >= 1; o >>= 1)
            s += __shfl_xor_sync(0xffffffffu, s, o);
        if (lane == 0) rowsum[wid * 16 + rr] = s;
    }
    __syncwarp();

    // epilogue: /rowsum, LayerNorm, leaky
    const int g = lane >> 2, q = lane & 3;
    const int rA = wid * 16 + g, rB = rA + 8;
    const float invA = 1.f / rowsum[rA];
    const float invB = 1.f / rowsum[rB];

    float vA[32], vB[32];
    float sA = 0.f, qA = 0.f, sB = 0.f, qB = 0.f;
#pragma unroll
    for (int nt = 0; nt < 16; nt++) {
        float a0 = acc[nt][0] * invA, a1 = acc[nt][1] * invA;
        float b0 = acc[nt][2] * invB, b1 = acc[nt][3] * invB;
        vA[nt * 2] = a0; vA[nt * 2 + 1] = a1;
        vB[nt * 2] = b0; vB[nt * 2 + 1] = b1;
        sA += a0 + a1; qA = fmaf(a0, a0, fmaf(a1, a1, qA));
        sB += b0 + b1; qB = fmaf(b0, b0, fmaf(b1, b1, qB));
    }
#pragma unroll
    for (int o = 2; o >= 1; o >>= 1) {
        sA += __shfl_xor_sync(0xffffffffu, sA, o);
        qA += __shfl_xor_sync(0xffffffffu, qA, o);
        sB += __shfl_xor_sync(0xffffffffu, sB, o);
        qB += __shfl_xor_sync(0xffffffffu, qB, o);
    }
    const float muA = sA * (1.f / 128.f);
    const float muB = sB * (1.f / 128.f);
    const float rsA = rsqrtf(qA * (1.f / 128.f) - muA * muA + 1e-5f);
    const float rsB = rsqrtf(qB * (1.f / 128.f) - muB * muB + 1e-5f);

    float* oA = out + ((size_t)(b * NNODE + n0 + rA)) * FEAT;
    float* oB = out + ((size_t)(b * NNODE + n0 + rB)) * FEAT;
#pragma unroll
    for (int nt = 0; nt < 16; nt++) {
        float zA0 = (vA[nt * 2] - muA) * rsA, zA1 = (vA[nt * 2 + 1] - muA) * rsA;
        float zB0 = (vB[nt * 2] - muB) * rsB, zB1 = (vB[nt * 2 + 1] - muB) * rsB;
        *(float2*)&oA[nt * 8 + q * 2] = make_float2(leakyf(zA0), leakyf(zA1));
        *(float2*)&oB[nt * 8 + q * 2] = make_float2(leakyf(zB0), leakyf(zB1));
    }
}

// ============================================================================
extern "C" void kernel_launch(void* const* d_in, const int* in_sizes, int n_in,
                              void* d_out, int out_size) {
    const float* h   = (const float*)d_in[0];
    const int*   adj = (const int*)d_in[1];
    const float* Ww  = (const float*)d_in[2];
    const float* Wb  = (const float*)d_in[3];
    const float* aw  = (const float*)d_in[4];
    float* out = (float*)d_out;

    k_prep<<<1, 128>>>(Ww, Wb, aw);
    cudaFuncSetAttribute(k_linear, cudaFuncAttributeMaxDynamicSharedMemorySize,
                         LIN_SMEM);
    k_linear<<<dim3(16, 8), 256, LIN_SMEM>>>(h, Ww, Wb);
    cudaFuncSetAttribute(k_attn, cudaFuncAttributeMaxDynamicSharedMemorySize,
                         ATTN_SMEM);
    k_attn<<<128, 256, ATTN_SMEM>>>(adj, out);
}

// round 8
// speedup vs baseline: 1.1791x; 1.1791x over previous
#include <cuda_runtime.h>
#include <cuda_fp16.h>
#include <cstdint>

#define BATCH 8
#define NNODE 2048
#define FEAT  128
#define LOG2E 1.4426950408889634f

// ---------------- device scratch (no allocations allowed) -------------------
__device__ __half g_wht[BATCH * FEAT * NNODE];  // WhT fp16, [b][f][n]
__device__ float g_wh1[BATCH * NNODE];          // Wh1 * LOG2E
__device__ float g_wh2[BATCH * NNODE];          // Wh2 * LOG2E
__device__ float g_w2bmax[BATCH * 16];          // per 128-block max of g_wh2
__device__ float g_u1[FEAT], g_u2[FEAT], g_c[2];

// ---------------- helpers ---------------------------------------------------
__device__ __forceinline__ float leakyf(float x) { return fmaxf(x, 0.2f * x); }

__device__ __forceinline__ uint32_t smem_u32(const void* p) {
    uint32_t a;
    asm("{ .reg .u64 t; cvta.to.shared.u64 t, %1; cvt.u32.u64 %0, t; }"
        : "=r"(a) : "l"(p));
    return a;
}

__device__ __forceinline__ uint32_t pack_h2(float x, float y) {
    __half2 v = __floats2half2_rn(x, y);
    return *reinterpret_cast<uint32_t*>(&v);
}

#define LDSM4(r, a)                                                            \
    asm volatile(                                                              \
        "ldmatrix.sync.aligned.m8n8.x4.shared.b16 {%0,%1,%2,%3}, [%4];"        \
        : "=r"((r)[0]), "=r"((r)[1]), "=r"((r)[2]), "=r"((r)[3])               \
        : "r"(a))

#define MMA16816(c, A, B0, B1)                                                 \
    asm volatile(                                                              \
        "mma.sync.aligned.m16n8k16.row.col.f32.f16.f16.f32 "                   \
        "{%0,%1,%2,%3}, {%4,%5,%6,%7}, {%8,%9}, {%0,%1,%2,%3};"                \
        : "+f"((c)[0]), "+f"((c)[1]), "+f"((c)[2]), "+f"((c)[3])               \
        : "r"((A)[0]), "r"((A)[1]), "r"((A)[2]), "r"((A)[3]),                  \
          "r"(B0), "r"(B1))

// ============================================================================
// k_prep (parallel): u1 = W^T a1, u2 = W^T a2, c = {b.a1, b.a2}
// grid(16) x 256 threads: warp w of block bk owns column k = bk*8 + w.
// ============================================================================
__global__ void k_prep(const float* __restrict__ W, const float* __restrict__ Wb,
                       const float* __restrict__ aw) {
    const int wid = threadIdx.x >> 5, lane = threadIdx.x & 31;
    const int k = blockIdx.x * 8 + wid;
    float s1 = 0.f, s2 = 0.f;
#pragma unroll
    for (int i = 0; i < 4; i++) {
        int f = lane + i * 32;
        float w = W[f * FEAT + k];
        s1 = fmaf(aw[f], w, s1);
        s2 = fmaf(aw[FEAT + f], w, s2);
    }
#pragma unroll
    for (int o = 16; o >= 1; o >>= 1) {
        s1 += __shfl_xor_sync(~0u, s1, o);
        s2 += __shfl_xor_sync(~0u, s2, o);
    }
    if (lane == 0) { g_u1[k] = s1; g_u2[k] = s2; }

    if (blockIdx.x == 0 && wid == 0) {
        float c1 = 0.f, c2 = 0.f;
#pragma unroll
        for (int i = 0; i < 4; i++) {
            int f = lane + i * 32;
            float b = Wb[f];
            c1 = fmaf(b, aw[f], c1);
            c2 = fmaf(b, aw[FEAT + f], c2);
        }
#pragma unroll
        for (int o = 16; o >= 1; o >>= 1) {
            c1 += __shfl_xor_sync(~0u, c1, o);
            c2 += __shfl_xor_sync(~0u, c2, o);
        }
        if (lane == 0) { g_c[0] = c1; g_c[1] = c2; }
    }
}

// ============================================================================
// k_linear: WhT[f][n] = sum_k W[f][k] h[n][k] + b[f]  via fp16 mma.sync.
// Scores via fp32 GEMV against u1/u2 (exact path). grid (16,8), 256 thr.
// ============================================================================
static constexpr int LIN_SMEM = 1024 + 128 * 132 * 4 + 2 * 32768;  // 134144

__global__ __launch_bounds__(256, 1) void k_linear(
    const float* __restrict__ h, const float* __restrict__ W,
    const float* __restrict__ Wb) {
    extern __shared__ __align__(16) char dynL[];
    float* u1s = (float*)dynL;            // 128
    float* u2s = u1s + 128;               // 128
    float* wm = u2s + 128;                // 8 warp maxes
    float* h32 = (float*)(dynL + 1024);   // [128][132]
    char* At = dynL + 1024 + 128 * 132 * 4;
    char* Bt = At + 32768;

    const int b = blockIdx.y, n0 = blockIdx.x * 128;
    const int t = threadIdx.x, lane = t & 31, wid = t >> 5;

    if (t < 128) { u1s[t] = g_u1[t]; u2s[t] = g_u2[t]; }

    // stage: h fp32 -> h32 ; W fp32 -> fp16 swizzled A tile
#pragma unroll
    for (int i = 0; i < 8; i++) {
        int idx = t + i * 256;  // chunk id 0..2047
        int row = idx >> 4;
        int x = idx & 15;
        const float* hp = &h[((size_t)(b * NNODE + n0 + row)) * FEAT + x * 8];
        float4 h0 = *(const float4*)hp;
        float4 h1 = *(const float4*)(hp + 4);
        *(float4*)&h32[row * 132 + x * 8] = h0;
        *(float4*)&h32[row * 132 + x * 8 + 4] = h1;
        const float* wp = &W[(size_t)row * FEAT + x * 8];
        float4 w0 = *(const float4*)wp;
        float4 w1 = *(const float4*)(wp + 4);
        uint4 pw;
        pw.x = pack_h2(w0.x, w0.y); pw.y = pack_h2(w0.z, w0.w);
        pw.z = pack_h2(w1.x, w1.y); pw.w = pack_h2(w1.z, w1.w);
        *(uint4*)(At + row * 256 + (((uint32_t)(x ^ (row & 7))) << 4)) = pw;
    }
    __syncthreads();

    // B tile (h fp16) from h32
#pragma unroll
    for (int i = 0; i < 8; i++) {
        int idx = t + i * 256;
        int row = idx >> 4;
        int x = idx & 15;
        float4 a0 = *(float4*)&h32[row * 132 + x * 8];
        float4 a1 = *(float4*)&h32[row * 132 + x * 8 + 4];
        uint4 p;
        p.x = pack_h2(a0.x, a0.y); p.y = pack_h2(a0.z, a0.w);
        p.z = pack_h2(a1.x, a1.y); p.w = pack_h2(a1.z, a1.w);
        *(uint4*)(Bt + row * 256 + (((uint32_t)(x ^ (row & 7))) << 4)) = p;
    }

    // GEMV: scores (fp32 exact)
    {
        const int row = t >> 1, k0 = (t & 1) * 64;
        float p1 = 0.f, p2 = 0.f;
#pragma unroll 8
        for (int k = 0; k < 64; k++) {
            float hv = h32[row * 132 + k0 + k];
            p1 = fmaf(hv, u1s[k0 + k], p1);
            p2 = fmaf(hv, u2s[k0 + k], p2);
        }
        p1 += __shfl_xor_sync(~0u, p1, 1);
        p2 += __shfl_xor_sync(~0u, p2, 1);
        float w2L = (p2 + g_c[1]) * LOG2E;
        if ((t & 1) == 0) {
            g_wh1[b * NNODE + n0 + row] = (p1 + g_c[0]) * LOG2E;
            g_wh2[b * NNODE + n0 + row] = w2L;
        }
        float m = w2L;
#pragma unroll
        for (int o = 16; o >= 1; o >>= 1)
            m = fmaxf(m, __shfl_xor_sync(~0u, m, o));
        if (lane == 0) wm[wid] = m;
    }
    __syncthreads();  // covers Bt staging + wm
    if (t == 0) {
        float mm = wm[0];
#pragma unroll
        for (int i = 1; i < 8; i++) mm = fmaxf(mm, wm[i]);
        g_w2bmax[b * 16 + blockIdx.x] = mm;
    }

    // ---- MMA: warp owns 16 f-rows, N=128 ----
    float acc[16][4];
#pragma unroll
    for (int nt = 0; nt < 16; nt++)
#pragma unroll
        for (int q = 0; q < 4; q++) acc[nt][q] = 0.f;

    const uint32_t At_a = smem_u32(At), Bt_a = smem_u32(Bt);
    const uint32_t aoff = (uint32_t)(wid * 16 + (lane & 7) + ((lane >> 3) & 1) * 8) * 256u;
    const uint32_t a_hk = lane >> 4, a_sw = lane & 7;
    const uint32_t boff = (uint32_t)(((lane >> 4) & 1) * 8 + (lane & 7)) * 256u;
    const uint32_t b_hk = (lane >> 3) & 1, b_sw = lane & 7;

#pragma unroll
    for (int kk = 0; kk < 8; kk++) {
        uint32_t ah[4];
        LDSM4(ah, At_a + aoff + ((((uint32_t)(kk * 2) + a_hk) ^ a_sw) << 4));
        uint32_t cb = (((uint32_t)(kk * 2) + b_hk) ^ b_sw) << 4;
#pragma unroll
        for (int ntp = 0; ntp < 8; ntp++) {
            uint32_t bh[4];
            LDSM4(bh, Bt_a + boff + (uint32_t)ntp * 4096u + cb);
            MMA16816(acc[ntp * 2], ah, bh[0], bh[1]);
            MMA16816(acc[ntp * 2 + 1], ah, bh[2], bh[3]);
        }
    }

    // epilogue: +bias, pack fp16, store WhT
    const int rA = wid * 16 + (lane >> 2), rB = rA + 8, q = lane & 3;
    const float biasA = Wb[rA], biasB = Wb[rB];
#pragma unroll
    for (int nt = 0; nt < 16; nt++) {
        uint32_t pa = pack_h2(acc[nt][0] + biasA, acc[nt][1] + biasA);
        uint32_t pb = pack_h2(acc[nt][2] + biasB, acc[nt][3] + biasB);
        *(uint32_t*)&g_wht[((size_t)(b * FEAT + rA)) * NNODE + n0 + nt * 8 + q * 2] = pa;
        *(uint32_t*)&g_wht[((size_t)(b * FEAT + rB)) * NNODE + n0 + nt * 8 + q * 2] = pb;
    }
}

// ============================================================================
// k_attn: per CTA = 128 query rows, 8 warps x 16 rows, full-width fp32 accum.
// One barrier per chunk; B tile double-buffered; A (P) tile warp-private.
// P exp via h2exp2 (f16x2), adjacency mask via bit-AND, rowsum in f16x2.
// ============================================================================
static constexpr int ATTN_SMEM = 1024 + 3 * 32768;  // 99328

__global__ __launch_bounds__(256, 1) void k_attn(const int* __restrict__ adj,
                                                 float* __restrict__ out) {
    extern __shared__ __align__(16) char dyn[];
    float* rowsum = (float*)dyn;            // 128 floats
    float* mxs = (float*)(dyn + 512);       // 16 floats
    char* atile = dyn + 1024;
    char* btile0 = atile + 32768;
    char* btile1 = btile0 + 32768;

    const int t = threadIdx.x;
    const int wid = t >> 5, lane = t & 31;
    const int b = blockIdx.x >> 4;
    const int n0 = (blockIdx.x & 15) << 7;

    if (t < 16) mxs[t] = g_w2bmax[b * 16 + t];
    __syncthreads();
    float mxL = mxs[0];
#pragma unroll
    for (int i = 1; i < 16; i++) mxL = fmaxf(mxL, mxs[i]);

    // per-row constants (log2 domain): y = max(c1+w2L, c2+0.2*w2L)
    float c1r[16], c2r[16];
#pragma unroll
    for (int rr = 0; rr < 16; rr++) {
        float w1L = g_wh1[b * NNODE + n0 + wid * 16 + rr];
        float xL = w1L + mxL;
        float MrL = fmaxf(xL, 0.2f * xL);
        c1r[rr] = w1L - MrL;
        c2r[rr] = 0.2f * w1L - MrL;
    }

    float acc[16][4];
#pragma unroll
    for (int nt = 0; nt < 16; nt++)
#pragma unroll
        for (int q = 0; q < 4; q++) acc[nt][q] = 0.f;
    __half2 s2acc[16];
#pragma unroll
    for (int rr = 0; rr < 16; rr++) s2acc[rr] = __half2half2(__ushort_as_half(0));

    const uint32_t atile_a = smem_u32(atile);
    const uint32_t aoff = (uint32_t)(wid * 16 + (lane & 7) + ((lane >> 3) & 1) * 8) * 256u;
    const uint32_t a_hk = lane >> 4, a_sw = lane & 7;
    const uint32_t boff = (uint32_t)(((lane >> 4) & 1) * 8 + (lane & 7)) * 256u;
    const uint32_t b_hk = (lane >> 3) & 1, b_sw = lane & 7;
    const uint32_t p_chunk = (uint32_t)(lane >> 1);
    const uint32_t p_half = (uint32_t)(lane & 1) * 8;
    const int jj = (lane & 15) * 8;
    const int bhalf = lane >> 4;

    auto stage_b = [&](int cc, char* buf) {
#pragma unroll
        for (int it = 0; it < 8; it++) {
            int f = wid * 16 + it * 2 + bhalf;
            uint4 vh = *(const uint4*)&g_wht[((size_t)(b * FEAT + f)) * NNODE + cc * 128 + jj];
            *(uint4*)(buf + (uint32_t)f * 256u +
                      ((((uint32_t)(lane & 15)) ^ (uint32_t)(f & 7)) << 4)) = vh;
        }
    };

    auto compute_p = [&](int cc) {
        const int j0 = cc * 128;
        const float4 w2v = *(const float4*)&g_wh2[b * NNODE + j0 + lane * 4];
        const float w2sx = 0.2f * w2v.x, w2sy = 0.2f * w2v.y;
        const float w2sz = 0.2f * w2v.z, w2sw = 0.2f * w2v.w;
        const int* arow = &adj[((size_t)(b * NNODE + n0 + wid * 16)) * NNODE + j0 + lane * 4];
#pragma unroll
        for (int rr = 0; rr < 16; rr++) {
            const int r = wid * 16 + rr;
            const float c1 = c1r[rr], c2 = c2r[rr];
            const int4 av = *(const int4*)(arow + (size_t)rr * NNODE);
            float y0 = fmaxf(c1 + w2v.x, c2 + w2sx);
            float y1 = fmaxf(c1 + w2v.y, c2 + w2sy);
            float y2 = fmaxf(c1 + w2v.z, c2 + w2sz);
            float y3 = fmaxf(c1 + w2v.w, c2 + w2sw);
            __half2 e01 = h2exp2(__floats2half2_rn(y0, y1));
            __half2 e23 = h2exp2(__floats2half2_rn(y2, y3));
            // adjacency mask: av in {0,1} -> -av is 0 or all-ones
            uint32_t m01 = (((uint32_t)(-av.x)) & 0x0000FFFFu) |
                           (((uint32_t)(-av.y)) & 0xFFFF0000u);
            uint32_t m23 = (((uint32_t)(-av.z)) & 0x0000FFFFu) |
                           (((uint32_t)(-av.w)) & 0xFFFF0000u);
            uint32_t p01 = *(uint32_t*)&e01 & m01;
            uint32_t p23 = *(uint32_t*)&e23 & m23;
            *(uint2*)(atile + (uint32_t)r * 256u +
                      ((p_chunk ^ (uint32_t)(r & 7)) << 4) + p_half) =
                make_uint2(p01, p23);
            s2acc[rr] = __hadd2(s2acc[rr],
                                __hadd2(*(__half2*)&p01, *(__half2*)&p23));
        }
    };

    // prologue: B0 + P0
    stage_b(0, btile0);
    compute_p(0);
    __syncthreads();

#pragma unroll 1
    for (int c = 0; c < 16; c++) {
        const uint32_t bt_a = smem_u32((c & 1) ? btile1 : btile0);
        // ---- MMA on chunk c ----
#pragma unroll 1
        for (int kk = 0; kk < 8; kk++) {
            uint32_t ah[4];
            LDSM4(ah, atile_a + aoff + ((((uint32_t)(kk * 2) + a_hk) ^ a_sw) << 4));
            uint32_t cb = (((uint32_t)(kk * 2) + b_hk) ^ b_sw) << 4;
#pragma unroll
            for (int ntp = 0; ntp < 8; ntp++) {
                uint32_t bh[4];
                LDSM4(bh, bt_a + boff + (uint32_t)ntp * 4096u + cb);
                MMA16816(acc[ntp * 2], ah, bh[0], bh[1]);
                MMA16816(acc[ntp * 2 + 1], ah, bh[2], bh[3]);
            }
        }
        if (c < 15) {
            stage_b(c + 1, (c & 1) ? btile0 : btile1);
            compute_p(c + 1);
            __syncthreads();
        }
    }

    // rowsum reduction (f16x2 lane-partials -> fp32)
#pragma unroll
    for (int rr = 0; rr < 16; rr++) {
        float2 sf = __half22float2(s2acc[rr]);
        float s = sf.x + sf.y;
#pragma unroll
        for (int o = 16; o >= 1; o >>= 1)
            s += __shfl_xor_sync(0xffffffffu, s, o);
        if (lane == 0) rowsum[wid * 16 + rr] = s;
    }
    __syncwarp();

    // epilogue: /rowsum, LayerNorm, leaky
    const int g = lane >> 2, q = lane & 3;
    const int rA = wid * 16 + g, rB = rA + 8;
    const float invA = 1.f / rowsum[rA];
    const float invB = 1.f / rowsum[rB];

    float vA[32], vB[32];
    float sA = 0.f, qA = 0.f, sB = 0.f, qB = 0.f;
#pragma unroll
    for (int nt = 0; nt < 16; nt++) {
        float a0 = acc[nt][0] * invA, a1 = acc[nt][1] * invA;
        float b0 = acc[nt][2] * invB, b1 = acc[nt][3] * invB;
        vA[nt * 2] = a0; vA[nt * 2 + 1] = a1;
        vB[nt * 2] = b0; vB[nt * 2 + 1] = b1;
        sA += a0 + a1; qA = fmaf(a0, a0, fmaf(a1, a1, qA));
        sB += b0 + b1; qB = fmaf(b0, b0, fmaf(b1, b1, qB));
    }
#pragma unroll
    for (int o = 2; o >= 1; o >>= 1) {
        sA += __shfl_xor_sync(0xffffffffu, sA, o);
        qA += __shfl_xor_sync(0xffffffffu, qA, o);
        sB += __shfl_xor_sync(0xffffffffu, sB, o);
        qB += __shfl_xor_sync(0xffffffffu, qB, o);
    }
    const float muA = sA * (1.f / 128.f);
    const float muB = sB * (1.f / 128.f);
    const float rsA = rsqrtf(qA * (1.f / 128.f) - muA * muA + 1e-5f);
    const float rsB = rsqrtf(qB * (1.f / 128.f) - muB * muB + 1e-5f);

    float* oA = out + ((size_t)(b * NNODE + n0 + rA)) * FEAT;
    float* oB = out + ((size_t)(b * NNODE + n0 + rB)) * FEAT;
#pragma unroll
    for (int nt = 0; nt < 16; nt++) {
        float zA0 = (vA[nt * 2] - muA) * rsA, zA1 = (vA[nt * 2 + 1] - muA) * rsA;
        float zB0 = (vB[nt * 2] - muB) * rsB, zB1 = (vB[nt * 2 + 1] - muB) * rsB;
        *(float2*)&oA[nt * 8 + q * 2] = make_float2(leakyf(zA0), leakyf(zA1));
        *(float2*)&oB[nt * 8 + q * 2] = make_float2(leakyf(zB0), leakyf(zB1));
    }
}

// ============================================================================
extern "C" void kernel_launch(void* const* d_in, const int* in_sizes, int n_in,
                              void* d_out, int out_size) {
    const float* h   = (const float*)d_in[0];
    const int*   adj = (const int*)d_in[1];
    const float* Ww  = (const float*)d_in[2];
    const float* Wb  = (const float*)d_in[3];
    const float* aw  = (const float*)d_in[4];
    float* out = (float*)d_out;

    k_prep<<<16, 256>>>(Ww, Wb, aw);
    cudaFuncSetAttribute(k_linear, cudaFuncAttributeMaxDynamicSharedMemorySize,
                         LIN_SMEM);
    k_linear<<<dim3(16, 8), 256, LIN_SMEM>>>(h, Ww, Wb);
    cudaFuncSetAttribute(k_attn, cudaFuncAttributeMaxDynamicSharedMemorySize,
                         ATTN_SMEM);
    k_attn<<<128, 256, ATTN_SMEM>>>(adj, out);
}

// round 10
// speedup vs baseline: 1.2101x; 1.0263x over previous
#include <cuda_runtime.h>
#include <cuda_fp16.h>
#include <cstdint>

#define BATCH 8
#define NNODE 2048
#define FEAT  128
#define LOG2E 1.4426950408889634f

// ---------------- device scratch (no allocations allowed) -------------------
__device__ __half g_wht[BATCH * FEAT * NNODE];  // WhT fp16, [b][f][n]
__device__ float g_wh1[BATCH * NNODE];          // Wh1 * LOG2E
__device__ float g_wh2[BATCH * NNODE];          // Wh2 * LOG2E
__device__ float g_w2bmax[BATCH * 16];          // per 128-block max of g_wh2

// ---------------- helpers ---------------------------------------------------
__device__ __forceinline__ float leakyf(float x) { return fmaxf(x, 0.2f * x); }

__device__ __forceinline__ uint32_t smem_u32(const void* p) {
    uint32_t a;
    asm("{ .reg .u64 t; cvta.to.shared.u64 t, %1; cvt.u32.u64 %0, t; }"
        : "=r"(a) : "l"(p));
    return a;
}

__device__ __forceinline__ uint32_t pack_h2(float x, float y) {
    __half2 v = __floats2half2_rn(x, y);
    return *reinterpret_cast<uint32_t*>(&v);
}

#define LDSM4(r, a)                                                            \
    asm volatile(                                                              \
        "ldmatrix.sync.aligned.m8n8.x4.shared.b16 {%0,%1,%2,%3}, [%4];"        \
        : "=r"((r)[0]), "=r"((r)[1]), "=r"((r)[2]), "=r"((r)[3])               \
        : "r"(a))

#define MMA16816(c, A, B0, B1)                                                 \
    asm volatile(                                                              \
        "mma.sync.aligned.m16n8k16.row.col.f32.f16.f16.f32 "                   \
        "{%0,%1,%2,%3}, {%4,%5,%6,%7}, {%8,%9}, {%0,%1,%2,%3};"                \
        : "+f"((c)[0]), "+f"((c)[1]), "+f"((c)[2]), "+f"((c)[3])               \
        : "r"((A)[0]), "r"((A)[1]), "r"((A)[2]), "r"((A)[3]),                  \
          "r"(B0), "r"(B1))

// ============================================================================
// k_linear: WhT[f][n] = sum_k W[f][k] h[n][k] + b[f]  via fp16 mma.sync.
// u1/u2/c1/c2 recomputed per-CTA (k_prep merged). Scores via fp32 GEMV.
// grid (16,8), 256 threads, per block: 128 rows x 128 feats of one batch.
// ============================================================================
static constexpr int LIN_SMEM = 2048 + 128 * 132 * 4 + 2 * 32768;  // 135168

__global__ __launch_bounds__(256, 1) void k_linear(
    const float* __restrict__ h, const float* __restrict__ W,
    const float* __restrict__ Wb, const float* __restrict__ aw) {
    extern __shared__ __align__(16) char dynL[];
    float* u1s = (float*)dynL;              // 128
    float* u2s = u1s + 128;                 // 128
    float* wm = u2s + 128;                  // 8
    float* cc = wm + 8;                     // 2 (c1, c2)
    float* h32 = (float*)(dynL + 2048);     // [128][132]
    char* At = dynL + 2048 + 128 * 132 * 4;
    char* Bt = At + 32768;
    float* up = (float*)Bt;  // temp partials: up1[2][128], up2[2][128] (2KB)

    const int b = blockIdx.y, n0 = blockIdx.x * 128;
    const int t = threadIdx.x, lane = t & 31, wid = t >> 5;

    // ---- phase 1: u partials (thread t: column k = t&127, f-half t>>7) ----
    {
        const int k = t & 127, fh = (t >> 7) * 64;
        float s1 = 0.f, s2 = 0.f;
#pragma unroll 8
        for (int f = 0; f < 64; f++) {
            float w = W[(size_t)(fh + f) * FEAT + k];
            s1 = fmaf(aw[fh + f], w, s1);
            s2 = fmaf(aw[FEAT + fh + f], w, s2);
        }
        up[(t >> 7) * 128 + k] = s1;
        up[256 + (t >> 7) * 128 + k] = s2;
        if (wid == 0) {
            float c1 = 0.f, c2 = 0.f;
#pragma unroll
            for (int i = 0; i < 4; i++) {
                int f = lane + i * 32;
                float bb = Wb[f];
                c1 = fmaf(bb, aw[f], c1);
                c2 = fmaf(bb, aw[FEAT + f], c2);
            }
#pragma unroll
            for (int o = 16; o >= 1; o >>= 1) {
                c1 += __shfl_xor_sync(~0u, c1, o);
                c2 += __shfl_xor_sync(~0u, c2, o);
            }
            if (lane == 0) { cc[0] = c1; cc[1] = c2; }
        }
    }
    __syncthreads();

    // ---- phase 2: finalize u; stage h32 + At ----
    if (t < 128) {
        u1s[t] = up[t] + up[128 + t];
        u2s[t] = up[256 + t] + up[384 + t];
    }
#pragma unroll
    for (int i = 0; i < 8; i++) {
        int idx = t + i * 256;  // chunk id 0..2047
        int row = idx >> 4;
        int x = idx & 15;
        const float* hp = &h[((size_t)(b * NNODE + n0 + row)) * FEAT + x * 8];
        float4 h0 = *(const float4*)hp;
        float4 h1 = *(const float4*)(hp + 4);
        *(float4*)&h32[row * 132 + x * 8] = h0;
        *(float4*)&h32[row * 132 + x * 8 + 4] = h1;
        const float* wp = &W[(size_t)row * FEAT + x * 8];
        float4 w0 = *(const float4*)wp;
        float4 w1 = *(const float4*)(wp + 4);
        uint4 pw;
        pw.x = pack_h2(w0.x, w0.y); pw.y = pack_h2(w0.z, w0.w);
        pw.z = pack_h2(w1.x, w1.y); pw.w = pack_h2(w1.z, w1.w);
        *(uint4*)(At + row * 256 + (((uint32_t)(x ^ (row & 7))) << 4)) = pw;
    }
    __syncthreads();

    // ---- phase 3: stage Bt (overwrites partials; consumed) + GEMV ----
#pragma unroll
    for (int i = 0; i < 8; i++) {
        int idx = t + i * 256;
        int row = idx >> 4;
        int x = idx & 15;
        float4 a0 = *(float4*)&h32[row * 132 + x * 8];
        float4 a1 = *(float4*)&h32[row * 132 + x * 8 + 4];
        uint4 p;
        p.x = pack_h2(a0.x, a0.y); p.y = pack_h2(a0.z, a0.w);
        p.z = pack_h2(a1.x, a1.y); p.w = pack_h2(a1.z, a1.w);
        *(uint4*)(Bt + row * 256 + (((uint32_t)(x ^ (row & 7))) << 4)) = p;
    }
    {
        const int row = t >> 1, k0 = (t & 1) * 64;
        float p1 = 0.f, p2 = 0.f;
#pragma unroll 8
        for (int k = 0; k < 64; k++) {
            float hv = h32[row * 132 + k0 + k];
            p1 = fmaf(hv, u1s[k0 + k], p1);
            p2 = fmaf(hv, u2s[k0 + k], p2);
        }
        p1 += __shfl_xor_sync(~0u, p1, 1);
        p2 += __shfl_xor_sync(~0u, p2, 1);
        float w2L = (p2 + cc[1]) * LOG2E;
        if ((t & 1) == 0) {
            g_wh1[b * NNODE + n0 + row] = (p1 + cc[0]) * LOG2E;
            g_wh2[b * NNODE + n0 + row] = w2L;
        }
        float m = w2L;
#pragma unroll
        for (int o = 16; o >= 1; o >>= 1)
            m = fmaxf(m, __shfl_xor_sync(~0u, m, o));
        if (lane == 0) wm[wid] = m;
    }
    __syncthreads();
    if (t == 0) {
        float mm = wm[0];
#pragma unroll
        for (int i = 1; i < 8; i++) mm = fmaxf(mm, wm[i]);
        g_w2bmax[b * 16 + blockIdx.x] = mm;
    }

    // ---- MMA: warp owns 16 f-rows, N=128 ----
    float acc[16][4];
#pragma unroll
    for (int nt = 0; nt < 16; nt++)
#pragma unroll
        for (int q = 0; q < 4; q++) acc[nt][q] = 0.f;

    const uint32_t At_a = smem_u32(At), Bt_a = smem_u32(Bt);
    const uint32_t aoff = (uint32_t)(wid * 16 + (lane & 7) + ((lane >> 3) & 1) * 8) * 256u;
    const uint32_t a_hk = lane >> 4, a_sw = lane & 7;
    const uint32_t boff = (uint32_t)(((lane >> 4) & 1) * 8 + (lane & 7)) * 256u;
    const uint32_t b_hk = (lane >> 3) & 1, b_sw = lane & 7;

#pragma unroll
    for (int kk = 0; kk < 8; kk++) {
        uint32_t ah[4];
        LDSM4(ah, At_a + aoff + ((((uint32_t)(kk * 2) + a_hk) ^ a_sw) << 4));
        uint32_t cb = (((uint32_t)(kk * 2) + b_hk) ^ b_sw) << 4;
#pragma unroll
        for (int ntp = 0; ntp < 8; ntp++) {
            uint32_t bh[4];
            LDSM4(bh, Bt_a + boff + (uint32_t)ntp * 4096u + cb);
            MMA16816(acc[ntp * 2], ah, bh[0], bh[1]);
            MMA16816(acc[ntp * 2 + 1], ah, bh[2], bh[3]);
        }
    }

    // epilogue: +bias, pack fp16, store WhT
    const int rA = wid * 16 + (lane >> 2), rB = rA + 8, q = lane & 3;
    const float biasA = Wb[rA], biasB = Wb[rB];
#pragma unroll
    for (int nt = 0; nt < 16; nt++) {
        uint32_t pa = pack_h2(acc[nt][0] + biasA, acc[nt][1] + biasA);
        uint32_t pb = pack_h2(acc[nt][2] + biasB, acc[nt][3] + biasB);
        *(uint32_t*)&g_wht[((size_t)(b * FEAT + rA)) * NNODE + n0 + nt * 8 + q * 2] = pa;
        *(uint32_t*)&g_wht[((size_t)(b * FEAT + rB)) * NNODE + n0 + nt * 8 + q * 2] = pb;
    }
}

// ============================================================================
// k_attn: per CTA = 128 query rows, 8 warps x 16 rows, full-width fp32 accum.
// Software pipeline: next chunk's B tile / adj rows / w2 prefetched into
// REGISTERS before the MMA block, consumed after (MMA hides global latency).
// ============================================================================
static constexpr int ATTN_SMEM = 1024 + 3 * 32768;  // 99328

__global__ __launch_bounds__(256, 1) void k_attn(const int* __restrict__ adj,
                                                 float* __restrict__ out) {
    extern __shared__ __align__(16) char dyn[];
    float* rowsum = (float*)dyn;            // 128 floats
    float* mxs = (float*)(dyn + 512);       // 16 floats
    char* atile = dyn + 1024;
    char* btile0 = atile + 32768;
    char* btile1 = btile0 + 32768;

    const int t = threadIdx.x;
    const int wid = t >> 5, lane = t & 31;
    const int b = blockIdx.x >> 4;
    const int n0 = (blockIdx.x & 15) << 7;

    if (t < 16) mxs[t] = g_w2bmax[b * 16 + t];
    __syncthreads();
    float mxL = mxs[0];
#pragma unroll
    for (int i = 1; i < 16; i++) mxL = fmaxf(mxL, mxs[i]);

    // per-row constants (log2 domain): y = max(c1+w2L, c2+0.2*w2L)
    float c1r[16], c2r[16];
#pragma unroll
    for (int rr = 0; rr < 16; rr++) {
        float w1L = g_wh1[b * NNODE + n0 + wid * 16 + rr];
        float xL = w1L + mxL;
        float MrL = fmaxf(xL, 0.2f * xL);
        c1r[rr] = w1L - MrL;
        c2r[rr] = 0.2f * w1L - MrL;
    }

    float acc[16][4];
#pragma unroll
    for (int nt = 0; nt < 16; nt++)
#pragma unroll
        for (int q = 0; q < 4; q++) acc[nt][q] = 0.f;
    __half2 s2acc[16];
#pragma unroll
    for (int rr = 0; rr < 16; rr++) s2acc[rr] = __half2half2(__ushort_as_half(0));

    const uint32_t atile_a = smem_u32(atile);
    const uint32_t aoff = (uint32_t)(wid * 16 + (lane & 7) + ((lane >> 3) & 1) * 8) * 256u;
    const uint32_t a_hk = lane >> 4, a_sw = lane & 7;
    const uint32_t boff = (uint32_t)(((lane >> 4) & 1) * 8 + (lane & 7)) * 256u;
    const uint32_t b_hk = (lane >> 3) & 1, b_sw = lane & 7;
    const uint32_t p_chunk = (uint32_t)(lane >> 1);
    const uint32_t p_half = (uint32_t)(lane & 1) * 8;
    const int jj = (lane & 15) * 8;
    const int bhalf = lane >> 4;

    // prefetch registers
    uint4 bp[8];
    int4 ap[16];
    float4 w2p;

    auto load_chunk = [&](int cc) {
#pragma unroll
        for (int it = 0; it < 8; it++) {
            int f = wid * 16 + it * 2 + bhalf;
            bp[it] = *(const uint4*)&g_wht[((size_t)(b * FEAT + f)) * NNODE + cc * 128 + jj];
        }
        const int* arow = &adj[((size_t)(b * NNODE + n0 + wid * 16)) * NNODE + cc * 128 + lane * 4];
#pragma unroll
        for (int rr = 0; rr < 16; rr++)
            ap[rr] = *(const int4*)(arow + (size_t)rr * NNODE);
        w2p = *(const float4*)&g_wh2[b * NNODE + cc * 128 + lane * 4];
    };

    auto sts_b = [&](char* buf) {
#pragma unroll
        for (int it = 0; it < 8; it++) {
            int f = wid * 16 + it * 2 + bhalf;
            *(uint4*)(buf + (uint32_t)f * 256u +
                      ((((uint32_t)(lane & 15)) ^ (uint32_t)(f & 7)) << 4)) = bp[it];
        }
    };

    auto compute_p = [&]() {
        const float w2sx = 0.2f * w2p.x, w2sy = 0.2f * w2p.y;
        const float w2sz = 0.2f * w2p.z, w2sw = 0.2f * w2p.w;
#pragma unroll
        for (int rr = 0; rr < 16; rr++) {
            const int r = wid * 16 + rr;
            const float c1 = c1r[rr], c2 = c2r[rr];
            const int4 av = ap[rr];
            float y0 = fmaxf(c1 + w2p.x, c2 + w2sx);
            float y1 = fmaxf(c1 + w2p.y, c2 + w2sy);
            float y2 = fmaxf(c1 + w2p.z, c2 + w2sz);
            float y3 = fmaxf(c1 + w2p.w, c2 + w2sw);
            __half2 e01 = h2exp2(__floats2half2_rn(y0, y1));
            __half2 e23 = h2exp2(__floats2half2_rn(y2, y3));
            uint32_t m01 = (((uint32_t)(-av.x)) & 0x0000FFFFu) |
                           (((uint32_t)(-av.y)) & 0xFFFF0000u);
            uint32_t m23 = (((uint32_t)(-av.z)) & 0x0000FFFFu) |
                           (((uint32_t)(-av.w)) & 0xFFFF0000u);
            uint32_t p01 = *(uint32_t*)&e01 & m01;
            uint32_t p23 = *(uint32_t*)&e23 & m23;
            *(uint2*)(atile + (uint32_t)r * 256u +
                      ((p_chunk ^ (uint32_t)(r & 7)) << 4) + p_half) =
                make_uint2(p01, p23);
            s2acc[rr] = __hadd2(s2acc[rr],
                                __hadd2(*(__half2*)&p01, *(__half2*)&p23));
        }
    };

    // prologue: chunk 0
    load_chunk(0);
    sts_b(btile0);
    compute_p();
    __syncthreads();

#pragma unroll 1
    for (int c = 0; c < 16; c++) {
        if (c < 15) load_chunk(c + 1);  // LDGs in flight during MMA
        const uint32_t bt_a = smem_u32((c & 1) ? btile1 : btile0);
#pragma unroll 1
        for (int kk = 0; kk < 8; kk++) {
            uint32_t ah[4];
            LDSM4(ah, atile_a + aoff + ((((uint32_t)(kk * 2) + a_hk) ^ a_sw) << 4));
            uint32_t cb = (((uint32_t)(kk * 2) + b_hk) ^ b_sw) << 4;
#pragma unroll
            for (int ntp = 0; ntp < 8; ntp++) {
                uint32_t bh[4];
                LDSM4(bh, bt_a + boff + (uint32_t)ntp * 4096u + cb);
                MMA16816(acc[ntp * 2], ah, bh[0], bh[1]);
                MMA16816(acc[ntp * 2 + 1], ah, bh[2], bh[3]);
            }
        }
        if (c < 15) {
            sts_b((c & 1) ? btile0 : btile1);
            compute_p();
            __syncthreads();
        }
    }

    // rowsum reduction (f16x2 lane-partials -> fp32)
#pragma unroll
    for (int rr = 0; rr < 16; rr++) {
        float2 sf = __half22float2(s2acc[rr]);
        float s = sf.x + sf.y;
#pragma unroll
        for (int o = 16; o >= 1; o >>= 1)
            s += __shfl_xor_sync(0xffffffffu, s, o);
        if (lane == 0) rowsum[wid * 16 + rr] = s;
    }
    __syncwarp();

    // epilogue: /rowsum, LayerNorm, leaky
    const int g = lane >> 2, q = lane & 3;
    const int rA = wid * 16 + g, rB = rA + 8;
    const float invA = 1.f / rowsum[rA];
    const float invB = 1.f / rowsum[rB];

    float vA[32], vB[32];
    float sA = 0.f, qA = 0.f, sB = 0.f, qB = 0.f;
#pragma unroll
    for (int nt = 0; nt < 16; nt++) {
        float a0 = acc[nt][0] * invA, a1 = acc[nt][1] * invA;
        float b0 = acc[nt][2] * invB, b1 = acc[nt][3] * invB;
        vA[nt * 2] = a0; vA[nt * 2 + 1] = a1;
        vB[nt * 2] = b0; vB[nt * 2 + 1] = b1;
        sA += a0 + a1; qA = fmaf(a0, a0, fmaf(a1, a1, qA));
        sB += b0 + b1; qB = fmaf(b0, b0, fmaf(b1, b1, qB));
    }
#pragma unroll
    for (int o = 2; o >= 1; o >>= 1) {
        sA += __shfl_xor_sync(0xffffffffu, sA, o);
        qA += __shfl_xor_sync(0xffffffffu, qA, o);
        sB += __shfl_xor_sync(0xffffffffu, sB, o);
        qB += __shfl_xor_sync(0xffffffffu, qB, o);
    }
    const float muA = sA * (1.f / 128.f);
    const float muB = sB * (1.f / 128.f);
    const float rsA = rsqrtf(qA * (1.f / 128.f) - muA * muA + 1e-5f);
    const float rsB = rsqrtf(qB * (1.f / 128.f) - muB * muB + 1e-5f);

    float* oA = out + ((size_t)(b * NNODE + n0 + rA)) * FEAT;
    float* oB = out + ((size_t)(b * NNODE + n0 + rB)) * FEAT;
#pragma unroll
    for (int nt = 0; nt < 16; nt++) {
        float zA0 = (vA[nt * 2] - muA) * rsA, zA1 = (vA[nt * 2 + 1] - muA) * rsA;
        float zB0 = (vB[nt * 2] - muB) * rsB, zB1 = (vB[nt * 2 + 1] - muB) * rsB;
        *(float2*)&oA[nt * 8 + q * 2] = make_float2(leakyf(zA0), leakyf(zA1));
        *(float2*)&oB[nt * 8 + q * 2] = make_float2(leakyf(zB0), leakyf(zB1));
    }
}

// ============================================================================
extern "C" void kernel_launch(void* const* d_in, const int* in_sizes, int n_in,
                              void* d_out, int out_size) {
    const float* h   = (const float*)d_in[0];
    const int*   adj = (const int*)d_in[1];
    const float* Ww  = (const float*)d_in[2];
    const float* Wb  = (const float*)d_in[3];
    const float* aw  = (const float*)d_in[4];
    float* out = (float*)d_out;

    cudaFuncSetAttribute(k_linear, cudaFuncAttributeMaxDynamicSharedMemorySize,
                         LIN_SMEM);
    k_linear<<<dim3(16, 8), 256, LIN_SMEM>>>(h, Ww, Wb, aw);
    cudaFuncSetAttribute(k_attn, cudaFuncAttributeMaxDynamicSharedMemorySize,
                         ATTN_SMEM);
    k_attn<<<128, 256, ATTN_SMEM>>>(adj, out);
}

// round 12
// speedup vs baseline: 1.3488x; 1.1146x over previous
#include <cuda_runtime.h>
#include <cuda_fp16.h>
#include <cstdint>

#define BATCH 8
#define NNODE 2048
#define FEAT  128
#define LOG2E 1.4426950408889634f

// ---------------- device scratch (no allocations allowed) -------------------
__device__ __half g_wht[BATCH * FEAT * NNODE];  // WhT fp16, [b][f][n]
__device__ float g_wh1[BATCH * NNODE];          // Wh1 * LOG2E
__device__ float g_wh2[BATCH * NNODE];          // Wh2 * LOG2E
__device__ float g_w2bmax[BATCH * 16];          // per 128-block max of g_wh2

// ---------------- helpers ---------------------------------------------------
__device__ __forceinline__ float leakyf(float x) { return fmaxf(x, 0.2f * x); }

__device__ __forceinline__ uint32_t smem_u32(const void* p) {
    uint32_t a;
    asm("{ .reg .u64 t; cvta.to.shared.u64 t, %1; cvt.u32.u64 %0, t; }"
        : "=r"(a) : "l"(p));
    return a;
}

__device__ __forceinline__ uint32_t pack_h2(float x, float y) {
    __half2 v = __floats2half2_rn(x, y);
    return *reinterpret_cast<uint32_t*>(&v);
}

#define CP_ASYNC16(dst, src)                                                   \
    asm volatile("cp.async.cg.shared.global [%0], [%1], 16;" ::"r"(dst),       \
                 "l"(src) : "memory")
#define CP_COMMIT() asm volatile("cp.async.commit_group;" ::: "memory")
#define CP_WAIT0() asm volatile("cp.async.wait_group 0;" ::: "memory")

#define LDSM4(r, a)                                                            \
    asm volatile(                                                              \
        "ldmatrix.sync.aligned.m8n8.x4.shared.b16 {%0,%1,%2,%3}, [%4];"        \
        : "=r"((r)[0]), "=r"((r)[1]), "=r"((r)[2]), "=r"((r)[3])               \
        : "r"(a))

#define MMA16816(c, A, B0, B1)                                                 \
    asm volatile(                                                              \
        "mma.sync.aligned.m16n8k16.row.col.f32.f16.f16.f32 "                   \
        "{%0,%1,%2,%3}, {%4,%5,%6,%7}, {%8,%9}, {%0,%1,%2,%3};"                \
        : "+f"((c)[0]), "+f"((c)[1]), "+f"((c)[2]), "+f"((c)[3])               \
        : "r"((A)[0]), "r"((A)[1]), "r"((A)[2]), "r"((A)[3]),                  \
          "r"(B0), "r"(B1))

// ============================================================================
// k_linear: WhT[f][n] = sum_k W[f][k] h[n][k] + b[f]  via fp16 mma.sync.
// u1/u2/c1/c2 recomputed per-CTA. Scores via fp32 GEMV (exact path).
// grid (16,8), 256 threads, per block: 128 rows x 128 feats of one batch.
// ============================================================================
static constexpr int LIN_SMEM = 2048 + 128 * 132 * 4 + 2 * 32768;  // 135168

__global__ __launch_bounds__(256, 1) void k_linear(
    const float* __restrict__ h, const float* __restrict__ W,
    const float* __restrict__ Wb, const float* __restrict__ aw) {
    extern __shared__ __align__(16) char dynL[];
    float* u1s = (float*)dynL;              // 128
    float* u2s = u1s + 128;                 // 128
    float* wm = u2s + 128;                  // 8
    float* cc = wm + 8;                     // 2 (c1, c2)
    float* h32 = (float*)(dynL + 2048);     // [128][132]
    char* At = dynL + 2048 + 128 * 132 * 4;
    char* Bt = At + 32768;
    float* up = (float*)Bt;  // temp partials: up1[2][128], up2[2][128] (2KB)

    const int b = blockIdx.y, n0 = blockIdx.x * 128;
    const int t = threadIdx.x, lane = t & 31, wid = t >> 5;

    // ---- phase 1: u partials (thread t: column k = t&127, f-half t>>7) ----
    {
        const int k = t & 127, fh = (t >> 7) * 64;
        float s1 = 0.f, s2 = 0.f;
#pragma unroll 8
        for (int f = 0; f < 64; f++) {
            float w = W[(size_t)(fh + f) * FEAT + k];
            s1 = fmaf(aw[fh + f], w, s1);
            s2 = fmaf(aw[FEAT + fh + f], w, s2);
        }
        up[(t >> 7) * 128 + k] = s1;
        up[256 + (t >> 7) * 128 + k] = s2;
        if (wid == 0) {
            float c1 = 0.f, c2 = 0.f;
#pragma unroll
            for (int i = 0; i < 4; i++) {
                int f = lane + i * 32;
                float bb = Wb[f];
                c1 = fmaf(bb, aw[f], c1);
                c2 = fmaf(bb, aw[FEAT + f], c2);
            }
#pragma unroll
            for (int o = 16; o >= 1; o >>= 1) {
                c1 += __shfl_xor_sync(~0u, c1, o);
                c2 += __shfl_xor_sync(~0u, c2, o);
            }
            if (lane == 0) { cc[0] = c1; cc[1] = c2; }
        }
    }
    __syncthreads();

    // ---- phase 2: finalize u; stage h32 + At ----
    if (t < 128) {
        u1s[t] = up[t] + up[128 + t];
        u2s[t] = up[256 + t] + up[384 + t];
    }
#pragma unroll
    for (int i = 0; i < 8; i++) {
        int idx = t + i * 256;  // chunk id 0..2047
        int row = idx >> 4;
        int x = idx & 15;
        const float* hp = &h[((size_t)(b * NNODE + n0 + row)) * FEAT + x * 8];
        float4 h0 = *(const float4*)hp;
        float4 h1 = *(const float4*)(hp + 4);
        *(float4*)&h32[row * 132 + x * 8] = h0;
        *(float4*)&h32[row * 132 + x * 8 + 4] = h1;
        const float* wp = &W[(size_t)row * FEAT + x * 8];
        float4 w0 = *(const float4*)wp;
        float4 w1 = *(const float4*)(wp + 4);
        uint4 pw;
        pw.x = pack_h2(w0.x, w0.y); pw.y = pack_h2(w0.z, w0.w);
        pw.z = pack_h2(w1.x, w1.y); pw.w = pack_h2(w1.z, w1.w);
        *(uint4*)(At + row * 256 + (((uint32_t)(x ^ (row & 7))) << 4)) = pw;
    }
    __syncthreads();

    // ---- phase 3: stage Bt (overwrites partials; consumed) + GEMV ----
#pragma unroll
    for (int i = 0; i < 8; i++) {
        int idx = t + i * 256;
        int row = idx >> 4;
        int x = idx & 15;
        float4 a0 = *(float4*)&h32[row * 132 + x * 8];
        float4 a1 = *(float4*)&h32[row * 132 + x * 8 + 4];
        uint4 p;
        p.x = pack_h2(a0.x, a0.y); p.y = pack_h2(a0.z, a0.w);
        p.z = pack_h2(a1.x, a1.y); p.w = pack_h2(a1.z, a1.w);
        *(uint4*)(Bt + row * 256 + (((uint32_t)(x ^ (row & 7))) << 4)) = p;
    }
    {
        const int row = t >> 1, k0 = (t & 1) * 64;
        float p1 = 0.f, p2 = 0.f;
#pragma unroll 8
        for (int k = 0; k < 64; k++) {
            float hv = h32[row * 132 + k0 + k];
            p1 = fmaf(hv, u1s[k0 + k], p1);
            p2 = fmaf(hv, u2s[k0 + k], p2);
        }
        p1 += __shfl_xor_sync(~0u, p1, 1);
        p2 += __shfl_xor_sync(~0u, p2, 1);
        float w2L = (p2 + cc[1]) * LOG2E;
        if ((t & 1) == 0) {
            g_wh1[b * NNODE + n0 + row] = (p1 + cc[0]) * LOG2E;
            g_wh2[b * NNODE + n0 + row] = w2L;
        }
        float m = w2L;
#pragma unroll
        for (int o = 16; o >= 1; o >>= 1)
            m = fmaxf(m, __shfl_xor_sync(~0u, m, o));
        if (lane == 0) wm[wid] = m;
    }
    __syncthreads();
    if (t == 0) {
        float mm = wm[0];
#pragma unroll
        for (int i = 1; i < 8; i++) mm = fmaxf(mm, wm[i]);
        g_w2bmax[b * 16 + blockIdx.x] = mm;
    }

    // ---- MMA: warp owns 16 f-rows, N=128 ----
    float acc[16][4];
#pragma unroll
    for (int nt = 0; nt < 16; nt++)
#pragma unroll
        for (int q = 0; q < 4; q++) acc[nt][q] = 0.f;

    const uint32_t At_a = smem_u32(At), Bt_a = smem_u32(Bt);
    const uint32_t aoff = (uint32_t)(wid * 16 + (lane & 7) + ((lane >> 3) & 1) * 8) * 256u;
    const uint32_t a_hk = lane >> 4, a_sw = lane & 7;
    const uint32_t boff = (uint32_t)(((lane >> 4) & 1) * 8 + (lane & 7)) * 256u;
    const uint32_t b_hk = (lane >> 3) & 1, b_sw = lane & 7;

#pragma unroll
    for (int kk = 0; kk < 8; kk++) {
        uint32_t ah[4];
        LDSM4(ah, At_a + aoff + ((((uint32_t)(kk * 2) + a_hk) ^ a_sw) << 4));
        uint32_t cb = (((uint32_t)(kk * 2) + b_hk) ^ b_sw) << 4;
#pragma unroll
        for (int ntp = 0; ntp < 8; ntp++) {
            uint32_t bh[4];
            LDSM4(bh, Bt_a + boff + (uint32_t)ntp * 4096u + cb);
            MMA16816(acc[ntp * 2], ah, bh[0], bh[1]);
            MMA16816(acc[ntp * 2 + 1], ah, bh[2], bh[3]);
        }
    }

    // epilogue: +bias, pack fp16, store WhT
    const int rA = wid * 16 + (lane >> 2), rB = rA + 8, q = lane & 3;
    const float biasA = Wb[rA], biasB = Wb[rB];
#pragma unroll
    for (int nt = 0; nt < 16; nt++) {
        uint32_t pa = pack_h2(acc[nt][0] + biasA, acc[nt][1] + biasA);
        uint32_t pb = pack_h2(acc[nt][2] + biasB, acc[nt][3] + biasB);
        *(uint32_t*)&g_wht[((size_t)(b * FEAT + rA)) * NNODE + n0 + nt * 8 + q * 2] = pa;
        *(uint32_t*)&g_wht[((size_t)(b * FEAT + rB)) * NNODE + n0 + nt * 8 + q * 2] = pb;
    }
}

// ============================================================================
// k_attn: per CTA = 128 query rows, 8 warps x 16 rows, full-width fp32 accum.
// cp.async pipeline: B tile (double-buffered, chunk cc -> btile[cc&1]) + adj
// chunk (single buffer, per-thread-exclusive slots) copied during MMA.
// ============================================================================
static constexpr int ATTN_SMEM = 1024 + 3 * 32768 + 65536;  // 164864

__global__ __launch_bounds__(256, 1) void k_attn(const int* __restrict__ adj,
                                                 float* __restrict__ out) {
    extern __shared__ __align__(16) char dyn[];
    float* rowsum = (float*)dyn;            // 128 floats
    float* mxs = (float*)(dyn + 512);       // 16 floats
    char* atile = dyn + 1024;
    char* btile0 = atile + 32768;
    char* btile1 = btile0 + 32768;
    char* adjs = btile1 + 32768;            // [128 rows][512B]

    const int t = threadIdx.x;
    const int wid = t >> 5, lane = t & 31;
    const int b = blockIdx.x >> 4;
    const int n0 = (blockIdx.x & 15) << 7;

    if (t < 16) mxs[t] = g_w2bmax[b * 16 + t];
    __syncthreads();
    float mxL = mxs[0];
#pragma unroll
    for (int i = 1; i < 16; i++) mxL = fmaxf(mxL, mxs[i]);

    // per-row constants (log2 domain): y = max(c1+w2L, c2+0.2*w2L)
    float c1r[16], c2r[16];
#pragma unroll
    for (int rr = 0; rr < 16; rr++) {
        float w1L = g_wh1[b * NNODE + n0 + wid * 16 + rr];
        float xL = w1L + mxL;
        float MrL = fmaxf(xL, 0.2f * xL);
        c1r[rr] = w1L - MrL;
        c2r[rr] = 0.2f * w1L - MrL;
    }

    float acc[16][4];
#pragma unroll
    for (int nt = 0; nt < 16; nt++)
#pragma unroll
        for (int q = 0; q < 4; q++) acc[nt][q] = 0.f;
    __half2 s2acc[16];
#pragma unroll
    for (int rr = 0; rr < 16; rr++) s2acc[rr] = __half2half2(__ushort_as_half(0));

    const uint32_t atile_a = smem_u32(atile);
    const uint32_t adjs_a = smem_u32(adjs);
    const uint32_t aoff = (uint32_t)(wid * 16 + (lane & 7) + ((lane >> 3) & 1) * 8) * 256u;
    const uint32_t a_hk = lane >> 4, a_sw = lane & 7;
    const uint32_t boff = (uint32_t)(((lane >> 4) & 1) * 8 + (lane & 7)) * 256u;
    const uint32_t b_hk = (lane >> 3) & 1, b_sw = lane & 7;
    const uint32_t p_chunk = (uint32_t)(lane >> 1);
    const uint32_t p_half = (uint32_t)(lane & 1) * 8;
    const int jj = (lane & 15) * 8;
    const int bhalf = lane >> 4;

    // per-thread adj SMEM slots: row (wid*16+rr), bytes lane*16..+15
    const uint32_t adj_dst0 = adjs_a + (uint32_t)(wid * 16) * 512u + (uint32_t)lane * 16u;
    const int* adj_src0 = &adj[((size_t)(b * NNODE + n0 + wid * 16)) * NNODE + lane * 4];

    auto issue_copies = [&](int cc, char* bbuf) {
        const uint32_t bb = smem_u32(bbuf);
#pragma unroll
        for (int it = 0; it < 8; it++) {
            int f = wid * 16 + it * 2 + bhalf;
            const __half* src = &g_wht[((size_t)(b * FEAT + f)) * NNODE + cc * 128 + jj];
            uint32_t dst = bb + (uint32_t)f * 256u +
                           ((((uint32_t)(lane & 15)) ^ (uint32_t)(f & 7)) << 4);
            CP_ASYNC16(dst, src);
        }
        const int* asrc = adj_src0 + cc * 128;
#pragma unroll
        for (int rr = 0; rr < 16; rr++)
            CP_ASYNC16(adj_dst0 + (uint32_t)rr * 512u, asrc + (size_t)rr * NNODE);
        CP_COMMIT();
    };

    auto compute_p = [&](float4 w2p) {
        const float w2sx = 0.2f * w2p.x, w2sy = 0.2f * w2p.y;
        const float w2sz = 0.2f * w2p.z, w2sw = 0.2f * w2p.w;
#pragma unroll
        for (int rr = 0; rr < 16; rr++) {
            const int r = wid * 16 + rr;
            const float c1 = c1r[rr], c2 = c2r[rr];
            const int4 av = *(const int4*)(adjs + (uint32_t)r * 512u + (uint32_t)lane * 16u);
            float y0 = fmaxf(c1 + w2p.x, c2 + w2sx);
            float y1 = fmaxf(c1 + w2p.y, c2 + w2sy);
            float y2 = fmaxf(c1 + w2p.z, c2 + w2sz);
            float y3 = fmaxf(c1 + w2p.w, c2 + w2sw);
            __half2 e01 = h2exp2(__floats2half2_rn(y0, y1));
            __half2 e23 = h2exp2(__floats2half2_rn(y2, y3));
            uint32_t m01 = (((uint32_t)(-av.x)) & 0x0000FFFFu) |
                           (((uint32_t)(-av.y)) & 0xFFFF0000u);
            uint32_t m23 = (((uint32_t)(-av.z)) & 0x0000FFFFu) |
                           (((uint32_t)(-av.w)) & 0xFFFF0000u);
            uint32_t p01 = *(uint32_t*)&e01 & m01;
            uint32_t p23 = *(uint32_t*)&e23 & m23;
            *(uint2*)(atile + (uint32_t)r * 256u +
                      ((p_chunk ^ (uint32_t)(r & 7)) << 4) + p_half) =
                make_uint2(p01, p23);
            s2acc[rr] = __hadd2(s2acc[rr],
                                __hadd2(*(__half2*)&p01, *(__half2*)&p23));
        }
    };

    // prologue: chunk 0 copies; then P(0); then issue chunk-1 copies
    issue_copies(0, btile0);
    float4 w2p = *(const float4*)&g_wh2[b * NNODE + lane * 4];
    CP_WAIT0();
    __syncthreads();
    compute_p(w2p);
    issue_copies(1, btile1);  // safe: this thread's adj reads already done
    __syncthreads();          // atile(0) visible

#pragma unroll 1
    for (int c = 0; c < 16; c++) {
        if (c < 15)  // prefetch next w2 (4 regs, in flight during MMA)
            w2p = *(const float4*)&g_wh2[b * NNODE + (c + 1) * 128 + lane * 4];
        const uint32_t bt_a = smem_u32((c & 1) ? btile1 : btile0);
#pragma unroll 1
        for (int kk = 0; kk < 8; kk++) {
            uint32_t ah[4];
            LDSM4(ah, atile_a + aoff + ((((uint32_t)(kk * 2) + a_hk) ^ a_sw) << 4));
            uint32_t cb = (((uint32_t)(kk * 2) + b_hk) ^ b_sw) << 4;
#pragma unroll
            for (int ntp = 0; ntp < 8; ntp++) {
                uint32_t bh[4];
                LDSM4(bh, bt_a + boff + (uint32_t)ntp * 4096u + cb);
                MMA16816(acc[ntp * 2], ah, bh[0], bh[1]);
                MMA16816(acc[ntp * 2 + 1], ah, bh[2], bh[3]);
            }
        }
        if (c < 15) {
            CP_WAIT0();       // chunk c+1 copies landed
            __syncthreads();  // visible to all; btile[c&1] free (MMA done)
            compute_p(w2p);
            // chunk c+2 -> btile[(c+2)&1] == btile[c&1]  (just freed by MMA(c))
            if (c < 14) issue_copies(c + 2, (c & 1) ? btile1 : btile0);
            __syncthreads();  // atile(c+1) visible
        }
    }

    // rowsum reduction (f16x2 lane-partials -> fp32)
#pragma unroll
    for (int rr = 0; rr < 16; rr++) {
        float2 sf = __half22float2(s2acc[rr]);
        float s = sf.x + sf.y;
#pragma unroll
        for (int o = 16; o >= 1; o >>= 1)
            s += __shfl_xor_sync(0xffffffffu, s, o);
        if (lane == 0) rowsum[wid * 16 + rr] = s;
    }
    __syncwarp();

    // epilogue: /rowsum, LayerNorm, leaky
    const int g = lane >> 2, q = lane & 3;
    const int rA = wid * 16 + g, rB = rA + 8;
    const float invA = 1.f / rowsum[rA];
    const float invB = 1.f / rowsum[rB];

    float vA[32], vB[32];
    float sA = 0.f, qA = 0.f, sB = 0.f, qB = 0.f;
#pragma unroll
    for (int nt = 0; nt < 16; nt++) {
        float a0 = acc[nt][0] * invA, a1 = acc[nt][1] * invA;
        float b0 = acc[nt][2] * invB, b1 = acc[nt][3] * invB;
        vA[nt * 2] = a0; vA[nt * 2 + 1] = a1;
        vB[nt * 2] = b0; vB[nt * 2 + 1] = b1;
        sA += a0 + a1; qA = fmaf(a0, a0, fmaf(a1, a1, qA));
        sB += b0 + b1; qB = fmaf(b0, b0, fmaf(b1, b1, qB));
    }
#pragma unroll
    for (int o = 2; o >= 1; o >>= 1) {
        sA += __shfl_xor_sync(0xffffffffu, sA, o);
        qA += __shfl_xor_sync(0xffffffffu, qA, o);
        sB += __shfl_xor_sync(0xffffffffu, sB, o);
        qB += __shfl_xor_sync(0xffffffffu, qB, o);
    }
    const float muA = sA * (1.f / 128.f);
    const float muB = sB * (1.f / 128.f);
    const float rsA = rsqrtf(qA * (1.f / 128.f) - muA * muA + 1e-5f);
    const float rsB = rsqrtf(qB * (1.f / 128.f) - muB * muB + 1e-5f);

    float* oA = out + ((size_t)(b * NNODE + n0 + rA)) * FEAT;
    float* oB = out + ((size_t)(b * NNODE + n0 + rB)) * FEAT;
#pragma unroll
    for (int nt = 0; nt < 16; nt++) {
        float zA0 = (vA[nt * 2] - muA) * rsA, zA1 = (vA[nt * 2 + 1] - muA) * rsA;
        float zB0 = (vB[nt * 2] - muB) * rsB, zB1 = (vB[nt * 2 + 1] - muB) * rsB;
        *(float2*)&oA[nt * 8 + q * 2] = make_float2(leakyf(zA0), leakyf(zA1));
        *(float2*)&oB[nt * 8 + q * 2] = make_float2(leakyf(zB0), leakyf(zB1));
    }
}

// ============================================================================
extern "C" void kernel_launch(void* const* d_in, const int* in_sizes, int n_in,
                              void* d_out, int out_size) {
    const float* h   = (const float*)d_in[0];
    const int*   adj = (const int*)d_in[1];
    const float* Ww  = (const float*)d_in[2];
    const float* Wb  = (const float*)d_in[3];
    const float* aw  = (const float*)d_in[4];
    float* out = (float*)d_out;

    cudaFuncSetAttribute(k_linear, cudaFuncAttributeMaxDynamicSharedMemorySize,
                         LIN_SMEM);
    k_linear<<<dim3(16, 8), 256, LIN_SMEM>>>(h, Ww, Wb, aw);
    cudaFuncSetAttribute(k_attn, cudaFuncAttributeMaxDynamicSharedMemorySize,
                         ATTN_SMEM);
    k_attn<<<128, 256, ATTN_SMEM>>>(adj, out);
}

// round 13
// speedup vs baseline: 1.3519x; 1.0023x over previous
#include <cuda_runtime.h>
#include <cuda_fp16.h>
#include <cstdint>

#define BATCH 8
#define NNODE 2048
#define FEAT  128
#define LOG2E 1.4426950408889634f

// ---------------- device scratch (no allocations allowed) -------------------
__device__ __half g_wht[BATCH * FEAT * NNODE];  // WhT fp16, [b][f][n]
__device__ float g_wh1[BATCH * NNODE];          // Wh1 * LOG2E
__device__ float g_wh2[BATCH * NNODE];          // Wh2 * LOG2E
__device__ float g_w2bmax[BATCH * 16];          // per 128-block max of g_wh2

// ---------------- helpers ---------------------------------------------------
__device__ __forceinline__ float leakyf(float x) { return fmaxf(x, 0.2f * x); }

__device__ __forceinline__ uint32_t smem_u32(const void* p) {
    uint32_t a;
    asm("{ .reg .u64 t; cvta.to.shared.u64 t, %1; cvt.u32.u64 %0, t; }"
        : "=r"(a) : "l"(p));
    return a;
}

__device__ __forceinline__ uint32_t pack_h2(float x, float y) {
    __half2 v = __floats2half2_rn(x, y);
    return *reinterpret_cast<uint32_t*>(&v);
}

#define CP_ASYNC16(dst, src)                                                   \
    asm volatile("cp.async.cg.shared.global [%0], [%1], 16;" ::"r"(dst),       \
                 "l"(src) : "memory")
#define CP_COMMIT() asm volatile("cp.async.commit_group;" ::: "memory")
#define CP_WAIT0() asm volatile("cp.async.wait_group 0;" ::: "memory")

#define LDSM4(r, a)                                                            \
    asm volatile(                                                              \
        "ldmatrix.sync.aligned.m8n8.x4.shared.b16 {%0,%1,%2,%3}, [%4];"        \
        : "=r"((r)[0]), "=r"((r)[1]), "=r"((r)[2]), "=r"((r)[3])               \
        : "r"(a))

#define MMA16816(c, A, B0, B1)                                                 \
    asm volatile(                                                              \
        "mma.sync.aligned.m16n8k16.row.col.f32.f16.f16.f32 "                   \
        "{%0,%1,%2,%3}, {%4,%5,%6,%7}, {%8,%9}, {%0,%1,%2,%3};"                \
        : "+f"((c)[0]), "+f"((c)[1]), "+f"((c)[2]), "+f"((c)[3])               \
        : "r"((A)[0]), "r"((A)[1]), "r"((A)[2]), "r"((A)[3]),                  \
          "r"(B0), "r"(B1))

// ============================================================================
// k_linear: WhT[f][n] = sum_k W[f][k] h[n][k] + b[f]  via fp16 mma.sync.
// u1/u2/c1/c2 recomputed per-CTA. Scores via fp32 GEMV (exact path).
// grid (16,8), 256 threads, per block: 128 rows x 128 feats of one batch.
// ============================================================================
static constexpr int LIN_SMEM = 2048 + 128 * 132 * 4 + 2 * 32768;  // 135168

__global__ __launch_bounds__(256, 1) void k_linear(
    const float* __restrict__ h, const float* __restrict__ W,
    const float* __restrict__ Wb, const float* __restrict__ aw) {
    extern __shared__ __align__(16) char dynL[];
    float* u1s = (float*)dynL;              // 128
    float* u2s = u1s + 128;                 // 128
    float* wm = u2s + 128;                  // 8
    float* cc = wm + 8;                     // 2 (c1, c2)
    float* h32 = (float*)(dynL + 2048);     // [128][132]
    char* At = dynL + 2048 + 128 * 132 * 4;
    char* Bt = At + 32768;
    float* up = (float*)Bt;  // temp partials: up1[2][128], up2[2][128] (2KB)

    const int b = blockIdx.y, n0 = blockIdx.x * 128;
    const int t = threadIdx.x, lane = t & 31, wid = t >> 5;

    // ---- phase 1: u partials (thread t: column k = t&127, f-half t>>7) ----
    {
        const int k = t & 127, fh = (t >> 7) * 64;
        float s1 = 0.f, s2 = 0.f;
#pragma unroll 8
        for (int f = 0; f < 64; f++) {
            float w = W[(size_t)(fh + f) * FEAT + k];
            s1 = fmaf(aw[fh + f], w, s1);
            s2 = fmaf(aw[FEAT + fh + f], w, s2);
        }
        up[(t >> 7) * 128 + k] = s1;
        up[256 + (t >> 7) * 128 + k] = s2;
        if (wid == 0) {
            float c1 = 0.f, c2 = 0.f;
#pragma unroll
            for (int i = 0; i < 4; i++) {
                int f = lane + i * 32;
                float bb = Wb[f];
                c1 = fmaf(bb, aw[f], c1);
                c2 = fmaf(bb, aw[FEAT + f], c2);
            }
#pragma unroll
            for (int o = 16; o >= 1; o >>= 1) {
                c1 += __shfl_xor_sync(~0u, c1, o);
                c2 += __shfl_xor_sync(~0u, c2, o);
            }
            if (lane == 0) { cc[0] = c1; cc[1] = c2; }
        }
    }
    __syncthreads();

    // ---- phase 2: finalize u; stage h32 + At ----
    if (t < 128) {
        u1s[t] = up[t] + up[128 + t];
        u2s[t] = up[256 + t] + up[384 + t];
    }
#pragma unroll
    for (int i = 0; i < 8; i++) {
        int idx = t + i * 256;  // chunk id 0..2047
        int row = idx >> 4;
        int x = idx & 15;
        const float* hp = &h[((size_t)(b * NNODE + n0 + row)) * FEAT + x * 8];
        float4 h0 = *(const float4*)hp;
        float4 h1 = *(const float4*)(hp + 4);
        *(float4*)&h32[row * 132 + x * 8] = h0;
        *(float4*)&h32[row * 132 + x * 8 + 4] = h1;
        const float* wp = &W[(size_t)row * FEAT + x * 8];
        float4 w0 = *(const float4*)wp;
        float4 w1 = *(const float4*)(wp + 4);
        uint4 pw;
        pw.x = pack_h2(w0.x, w0.y); pw.y = pack_h2(w0.z, w0.w);
        pw.z = pack_h2(w1.x, w1.y); pw.w = pack_h2(w1.z, w1.w);
        *(uint4*)(At + row * 256 + (((uint32_t)(x ^ (row & 7))) << 4)) = pw;
    }
    __syncthreads();

    // ---- phase 3: stage Bt (overwrites partials; consumed) + GEMV ----
#pragma unroll
    for (int i = 0; i < 8; i++) {
        int idx = t + i * 256;
        int row = idx >> 4;
        int x = idx & 15;
        float4 a0 = *(float4*)&h32[row * 132 + x * 8];
        float4 a1 = *(float4*)&h32[row * 132 + x * 8 + 4];
        uint4 p;
        p.x = pack_h2(a0.x, a0.y); p.y = pack_h2(a0.z, a0.w);
        p.z = pack_h2(a1.x, a1.y); p.w = pack_h2(a1.z, a1.w);
        *(uint4*)(Bt + row * 256 + (((uint32_t)(x ^ (row & 7))) << 4)) = p;
    }
    {
        const int row = t >> 1, k0 = (t & 1) * 64;
        float p1 = 0.f, p2 = 0.f;
#pragma unroll 8
        for (int k = 0; k < 64; k++) {
            float hv = h32[row * 132 + k0 + k];
            p1 = fmaf(hv, u1s[k0 + k], p1);
            p2 = fmaf(hv, u2s[k0 + k], p2);
        }
        p1 += __shfl_xor_sync(~0u, p1, 1);
        p2 += __shfl_xor_sync(~0u, p2, 1);
        float w2L = (p2 + cc[1]) * LOG2E;
        if ((t & 1) == 0) {
            g_wh1[b * NNODE + n0 + row] = (p1 + cc[0]) * LOG2E;
            g_wh2[b * NNODE + n0 + row] = w2L;
        }
        float m = w2L;
#pragma unroll
        for (int o = 16; o >= 1; o >>= 1)
            m = fmaxf(m, __shfl_xor_sync(~0u, m, o));
        if (lane == 0) wm[wid] = m;
    }
    __syncthreads();
    if (t == 0) {
        float mm = wm[0];
#pragma unroll
        for (int i = 1; i < 8; i++) mm = fmaxf(mm, wm[i]);
        g_w2bmax[b * 16 + blockIdx.x] = mm;
    }

    // ---- MMA: warp owns 16 f-rows, N=128 ----
    float acc[16][4];
#pragma unroll
    for (int nt = 0; nt < 16; nt++)
#pragma unroll
        for (int q = 0; q < 4; q++) acc[nt][q] = 0.f;

    const uint32_t At_a = smem_u32(At), Bt_a = smem_u32(Bt);
    const uint32_t aoff = (uint32_t)(wid * 16 + (lane & 7) + ((lane >> 3) & 1) * 8) * 256u;
    const uint32_t a_hk = lane >> 4, a_sw = lane & 7;
    const uint32_t boff = (uint32_t)(((lane >> 4) & 1) * 8 + (lane & 7)) * 256u;
    const uint32_t b_hk = (lane >> 3) & 1, b_sw = lane & 7;

#pragma unroll
    for (int kk = 0; kk < 8; kk++) {
        uint32_t ah[4];
        LDSM4(ah, At_a + aoff + ((((uint32_t)(kk * 2) + a_hk) ^ a_sw) << 4));
        uint32_t cb = (((uint32_t)(kk * 2) + b_hk) ^ b_sw) << 4;
#pragma unroll
        for (int ntp = 0; ntp < 8; ntp++) {
            uint32_t bh[4];
            LDSM4(bh, Bt_a + boff + (uint32_t)ntp * 4096u + cb);
            MMA16816(acc[ntp * 2], ah, bh[0], bh[1]);
            MMA16816(acc[ntp * 2 + 1], ah, bh[2], bh[3]);
        }
    }

    // epilogue: +bias, pack fp16, store WhT
    const int rA = wid * 16 + (lane >> 2), rB = rA + 8, q = lane & 3;
    const float biasA = Wb[rA], biasB = Wb[rB];
#pragma unroll
    for (int nt = 0; nt < 16; nt++) {
        uint32_t pa = pack_h2(acc[nt][0] + biasA, acc[nt][1] + biasA);
        uint32_t pb = pack_h2(acc[nt][2] + biasB, acc[nt][3] + biasB);
        *(uint32_t*)&g_wht[((size_t)(b * FEAT + rA)) * NNODE + n0 + nt * 8 + q * 2] = pa;
        *(uint32_t*)&g_wht[((size_t)(b * FEAT + rB)) * NNODE + n0 + nt * 8 + q * 2] = pb;
    }
}

// ============================================================================
// k_attn v2: CTA = 64 query rows, 4 warps, chunk = 64 keys, 2 CTAs/SM.
// Warp tiling 2x2: warp (mg,ng) = rows mg*32..+32, feats ng*64..+64.
// cp.async pipeline: B tile double-buffered (chunk cc -> btile[cc&1]),
// adj single buffer (per-thread-exclusive slots). Epilogue LN via SMEM
// exchange (feature halves live in different warps).
// SMEM map: atile[0,8K) btile0[8K,24K) btile1[24K,40K) adjs[40K,56K)
// Overlays (after last use): mxs/rowsum @0, vsm @8K.
// ============================================================================
static constexpr int ATTN_SMEM = 57344;  // 56KB -> 2 CTAs/SM

__global__ __launch_bounds__(128, 2) void k_attn(const int* __restrict__ adj,
                                                 float* __restrict__ out) {
    extern __shared__ __align__(16) char dyn[];
    char* atile = dyn;
    char* btile0 = dyn + 8192;
    char* btile1 = dyn + 24576;
    char* adjs = dyn + 40960;

    const int t = threadIdx.x;
    const int wid = t >> 5, lane = t & 31;
    const int b = blockIdx.x >> 5;
    const int n0 = (blockIdx.x & 31) << 6;

    // batch max (overlay in atile; consumed before any atile write)
    float* mxs = (float*)dyn;
    if (t < 16) mxs[t] = g_w2bmax[b * 16 + t];
    __syncthreads();
    float mxL = mxs[0];
#pragma unroll
    for (int i = 1; i < 16; i++) mxL = fmaxf(mxL, mxs[i]);
    __syncthreads();

    // per-row constants (log2 domain), rows wid*16 + rr
    float c1r[16], c2r[16];
#pragma unroll
    for (int rr = 0; rr < 16; rr++) {
        float w1L = g_wh1[b * NNODE + n0 + wid * 16 + rr];
        float xL = w1L + mxL;
        float MrL = fmaxf(xL, 0.2f * xL);
        c1r[rr] = w1L - MrL;
        c2r[rr] = 0.2f * w1L - MrL;
    }

    // accumulators: acc[mt*8+nt]; warp (mg,ng)
    const int mg = wid >> 1, ng = wid & 1;
    float acc[16][4];
#pragma unroll
    for (int nt = 0; nt < 16; nt++)
#pragma unroll
        for (int q = 0; q < 4; q++) acc[nt][q] = 0.f;
    __half2 s2acc[8];
#pragma unroll
    for (int rr = 0; rr < 8; rr++) s2acc[rr] = __half2half2(__ushort_as_half(0));

    const uint32_t atile_a = smem_u32(atile);
    const uint32_t adjs_a = smem_u32(adjs);
    // A: rows mg*32 + mt*16 + (lane&7) + ((lane>>3)&1)*8 ; swizzle key = lane&7
    const uint32_t a_row = (uint32_t)(mg * 32 + (lane & 7) + ((lane >> 3) & 1) * 8);
    const uint32_t a_hk = lane >> 4, a_sw = lane & 7;
    const uint32_t aoff0 = a_row * 128u, aoff1 = (a_row + 16) * 128u;
    // B: f rows ng*64 + ntp*16 + ((lane>>4)&1)*8 + (lane&7)
    const uint32_t b_row = (uint32_t)(ng * 64 + ((lane >> 4) & 1) * 8 + (lane & 7));
    const uint32_t b_hk = (lane >> 3) & 1, b_sw = lane & 7;
    const uint32_t boff = b_row * 128u;

    // adj slots: reader/copier thread identity: row wid*16 + rr*2 + (lane>>4),
    // 16B at (lane&15)*16; rr stride = 2 rows = 512B smem / 2*NNODE global
    const uint32_t adj_dst0 =
        adjs_a + (uint32_t)(wid * 16 + (lane >> 4)) * 256u + (uint32_t)(lane & 15) * 16u;
    const int* adj_src0 =
        &adj[((size_t)(b * NNODE + n0 + wid * 16 + (lane >> 4))) * NNODE + (lane & 15) * 4];

    auto issue_copies = [&](int cc, char* bbuf) {
        const uint32_t bb = smem_u32(bbuf);
#pragma unroll
        for (int it = 0; it < 8; it++) {
            int f = it * 16 + (t >> 3);
            const __half* src = &g_wht[((size_t)(b * FEAT + f)) * NNODE + cc * 64 + (t & 7) * 8];
            uint32_t dst = bb + (uint32_t)f * 128u +
                           ((((uint32_t)(t & 7)) ^ (uint32_t)(f & 7)) << 4);
            CP_ASYNC16(dst, src);
        }
        const int* asrc = adj_src0 + cc * 64;
#pragma unroll
        for (int rr = 0; rr < 8; rr++)
            CP_ASYNC16(adj_dst0 + (uint32_t)rr * 512u, asrc + (size_t)rr * 2 * NNODE);
        CP_COMMIT();
    };

    auto compute_p = [&](float4 w2v) {
        const float w2sx = 0.2f * w2v.x, w2sy = 0.2f * w2v.y;
        const float w2sz = 0.2f * w2v.z, w2sw = 0.2f * w2v.w;
        const int rh = lane >> 4;
#pragma unroll
        for (int rr = 0; rr < 8; rr++) {
            const int r = wid * 16 + rr * 2 + rh;
            const float c1 = c1r[rr * 2 + rh], c2 = c2r[rr * 2 + rh];
            const int4 av = *(const int4*)(adjs + (uint32_t)r * 256u + (uint32_t)(lane & 15) * 16u);
            float y0 = fmaxf(c1 + w2v.x, c2 + w2sx);
            float y1 = fmaxf(c1 + w2v.y, c2 + w2sy);
            float y2 = fmaxf(c1 + w2v.z, c2 + w2sz);
            float y3 = fmaxf(c1 + w2v.w, c2 + w2sw);
            __half2 e01 = h2exp2(__floats2half2_rn(y0, y1));
            __half2 e23 = h2exp2(__floats2half2_rn(y2, y3));
            uint32_t m01 = (((uint32_t)(-av.x)) & 0x0000FFFFu) |
                           (((uint32_t)(-av.y)) & 0xFFFF0000u);
            uint32_t m23 = (((uint32_t)(-av.z)) & 0x0000FFFFu) |
                           (((uint32_t)(-av.w)) & 0xFFFF0000u);
            uint32_t p01 = *(uint32_t*)&e01 & m01;
            uint32_t p23 = *(uint32_t*)&e23 & m23;
            *(uint2*)(atile + (uint32_t)r * 128u +
                      ((((uint32_t)((lane & 15) >> 1)) ^ (uint32_t)(r & 7)) << 4) +
                      (uint32_t)(lane & 1) * 8u) = make_uint2(p01, p23);
            s2acc[rr] = __hadd2(s2acc[rr],
                                __hadd2(*(__half2*)&p01, *(__half2*)&p23));
        }
    };

    // prologue: chunk 0
    issue_copies(0, btile0);
    float4 w2p = *(const float4*)&g_wh2[b * NNODE + (lane & 15) * 4];
    CP_WAIT0();
    __syncthreads();
    compute_p(w2p);
    issue_copies(1, btile1);
    __syncthreads();

#pragma unroll 1
    for (int c = 0; c < 32; c++) {
        if (c < 31)
            w2p = *(const float4*)&g_wh2[b * NNODE + (c + 1) * 64 + (lane & 15) * 4];
        const uint32_t bt_a = smem_u32((c & 1) ? btile1 : btile0);
#pragma unroll 1
        for (int kk = 0; kk < 4; kk++) {
            uint32_t ah0[4], ah1[4];
            uint32_t ca = ((((uint32_t)(kk * 2)) + a_hk) ^ a_sw) << 4;
            LDSM4(ah0, atile_a + aoff0 + ca);
            LDSM4(ah1, atile_a + aoff1 + ca);
            uint32_t cb = ((((uint32_t)(kk * 2)) + b_hk) ^ b_sw) << 4;
#pragma unroll
            for (int ntp = 0; ntp < 4; ntp++) {
                uint32_t bh[4];
                LDSM4(bh, bt_a + boff + (uint32_t)ntp * 2048u + cb);
                MMA16816(acc[ntp * 2], ah0, bh[0], bh[1]);
                MMA16816(acc[ntp * 2 + 1], ah0, bh[2], bh[3]);
                MMA16816(acc[8 + ntp * 2], ah1, bh[0], bh[1]);
                MMA16816(acc[8 + ntp * 2 + 1], ah1, bh[2], bh[3]);
            }
        }
        if (c < 31) {
            CP_WAIT0();
            __syncthreads();
            compute_p(w2p);
            if (c < 30) issue_copies(c + 2, (c & 1) ? btile1 : btile0);
            __syncthreads();
        }
    }

    // ---- epilogue ----
    __syncthreads();  // all MMA done before overlaying atile/btile/adjs

    // rowsum -> smem (overlay at atile)
    float* rowsum = (float*)dyn;
#pragma unroll
    for (int rr = 0; rr < 8; rr++) {
        float2 sf = __half22float2(s2acc[rr]);
        float s = sf.x + sf.y;
#pragma unroll
        for (int o = 8; o >= 1; o >>= 1)
            s += __shfl_xor_sync(0xffffffffu, s, o);  // reduce within 16-lane group
        if ((lane & 15) == 0) rowsum[wid * 16 + rr * 2 + (lane >> 4)] = s;
    }
    __syncthreads();

    // normalized values -> vsm[64][132] (overlay at btile/adj region)
    float* vsm = (float*)(dyn + 8192);
#pragma unroll
    for (int mt = 0; mt < 2; mt++) {
        const int rA = mg * 32 + mt * 16 + (lane >> 2), rB = rA + 8;
        const float invA = 1.f / rowsum[rA];
        const float invB = 1.f / rowsum[rB];
#pragma unroll
        for (int nt = 0; nt < 8; nt++) {
            const int col = ng * 64 + nt * 8 + (lane & 3) * 2;
            vsm[rA * 132 + col] = acc[mt * 8 + nt][0] * invA;
            vsm[rA * 132 + col + 1] = acc[mt * 8 + nt][1] * invA;
            vsm[rB * 132 + col] = acc[mt * 8 + nt][2] * invB;
            vsm[rB * 132 + col + 1] = acc[mt * 8 + nt][3] * invB;
        }
    }
    __syncthreads();

    // LayerNorm + leaky: lane pair handles one row (half features each)
    {
        const int row = wid * 16 + (lane >> 1);
        const int hb = (lane & 1) * 64;
        float s = 0.f, q = 0.f;
#pragma unroll
        for (int i = 0; i < 16; i++) {
            float4 x = *(float4*)&vsm[row * 132 + hb + i * 4];
            s += (x.x + x.y) + (x.z + x.w);
            q = fmaf(x.x, x.x, fmaf(x.y, x.y, fmaf(x.z, x.z, fmaf(x.w, x.w, q))));
        }
        s += __shfl_xor_sync(0xffffffffu, s, 1);
        q += __shfl_xor_sync(0xffffffffu, q, 1);
        const float mu = s * (1.f / 128.f);
        const float rstd = rsqrtf(q * (1.f / 128.f) - mu * mu + 1e-5f);
        float* orow = out + ((size_t)(b * NNODE + n0 + row)) * FEAT + hb;
#pragma unroll
        for (int i = 0; i < 16; i++) {
            float4 x = *(float4*)&vsm[row * 132 + hb + i * 4];
            float4 z;
            z.x = leakyf((x.x - mu) * rstd);
            z.y = leakyf((x.y - mu) * rstd);
            z.z = leakyf((x.z - mu) * rstd);
            z.w = leakyf((x.w - mu) * rstd);
            *(float4*)&orow[i * 4] = z;
        }
    }
}

// ============================================================================
extern "C" void kernel_launch(void* const* d_in, const int* in_sizes, int n_in,
                              void* d_out, int out_size) {
    const float* h   = (const float*)d_in[0];
    const int*   adj = (const int*)d_in[1];
    const float* Ww  = (const float*)d_in[2];
    const float* Wb  = (const float*)d_in[3];
    const float* aw  = (const float*)d_in[4];
    float* out = (float*)d_out;

    cudaFuncSetAttribute(k_linear, cudaFuncAttributeMaxDynamicSharedMemorySize,
                         LIN_SMEM);
    k_linear<<<dim3(16, 8), 256, LIN_SMEM>>>(h, Ww, Wb, aw);
    cudaFuncSetAttribute(k_attn, cudaFuncAttributeMaxDynamicSharedMemorySize,
                         ATTN_SMEM);
    k_attn<<<256, 128, ATTN_SMEM>>>(adj, out);
}